// round 12
// baseline (speedup 1.0000x reference)
#include <cuda_runtime.h>
#include <cuda_bf16.h>
#include <cstdint>
#include <cstddef>

// ---------------------------------------------------------------------------
// Merge_MixtralSparseMoeBlock — weight-folded, bf16 hi/lo split (3 passes):
//   W1' = w1 + u1@v1 ; W3' = w3 + u3@v3 ; W2' = w2 + u2@v2   (one prep launch)
//   gate = x@W1'^T ; up = x@W3'^T  (fused, shared A tiles)
//   h = silu(gate)*up  (fused epilogue -> bf16 hi/lo planes)
//   out = h@W2'^T ; logits = x@gate_w^T
// R12: R8 GEMM core (best) + SMEM-cached logits + vectorized x-split.
// ---------------------------------------------------------------------------

#define NTOK 8192
#define HDIM 2048
#define IDIM 7168
#define RDIM 398
#define RPAD 448

// ---------------- device scratch -------------------------------------------
__device__ __align__(16) __nv_bfloat16 g_xs  [2ull * NTOK * HDIM];
__device__ __align__(16) __nv_bfloat16 g_u1s [2ull * IDIM * RPAD];
__device__ __align__(16) __nv_bfloat16 g_u3s [2ull * IDIM * RPAD];
__device__ __align__(16) __nv_bfloat16 g_u2s [2ull * HDIM * RPAD];
__device__ __align__(16) __nv_bfloat16 g_v1ts[2ull * HDIM * RPAD];
__device__ __align__(16) __nv_bfloat16 g_v3ts[2ull * HDIM * RPAD];
__device__ __align__(16) __nv_bfloat16 g_v2ts[2ull * IDIM * RPAD];
__device__ __align__(16) __nv_bfloat16 g_w1ps[2ull * IDIM * HDIM];
__device__ __align__(16) __nv_bfloat16 g_w3ps[2ull * IDIM * HDIM];
__device__ __align__(16) __nv_bfloat16 g_w2ps[2ull * HDIM * IDIM];
__device__ __align__(16) __nv_bfloat16 g_hs  [2ull * NTOK * IDIM];

// ---------------- PTX helpers ----------------------------------------------
__device__ __forceinline__ uint32_t smem_u32(const void* p) {
    uint32_t a;
    asm("{ .reg .u64 t; cvta.to.shared.u64 t, %1; cvt.u32.u64 %0, t; }"
        : "=r"(a) : "l"(p));
    return a;
}
__device__ __forceinline__ void ldsm_x4(uint32_t* r, uint32_t addr) {
    asm volatile("ldmatrix.sync.aligned.m8n8.x4.shared.b16 {%0,%1,%2,%3}, [%4];"
                 : "=r"(r[0]), "=r"(r[1]), "=r"(r[2]), "=r"(r[3]) : "r"(addr));
}
__device__ __forceinline__ void mma_bf16(float* d, const uint32_t* a, const uint32_t* b) {
    asm volatile("mma.sync.aligned.m16n8k16.row.col.f32.bf16.bf16.f32 "
                 "{%0,%1,%2,%3}, {%4,%5,%6,%7}, {%8,%9}, {%0,%1,%2,%3};"
                 : "+f"(d[0]), "+f"(d[1]), "+f"(d[2]), "+f"(d[3])
                 : "r"(a[0]), "r"(a[1]), "r"(a[2]), "r"(a[3]),
                   "r"(b[0]), "r"(b[1]));
}
#define CP_COMMIT() asm volatile("cp.async.commit_group;" ::: "memory")
#define CP_WAIT1()  asm volatile("cp.async.wait_group 1;" ::: "memory")

// BK=64 rows are 128B (8 x 16B chunks); chunk' = c ^ (r&7) is conflict-free.
__device__ __forceinline__ uint32_t swz(int r, int c) {
    return (uint32_t)(r * 128 + ((c ^ (r & 7)) << 4));
}
__device__ __forceinline__ float siluf(float x) { return x / (1.f + __expf(-x)); }

// pack two fp32 into hi/lo bf16x2 words
__device__ __forceinline__ void split2(float v0, float v1,
                                       __nv_bfloat162& h, __nv_bfloat162& l) {
    __nv_bfloat16 h0 = __float2bfloat16(v0), h1 = __float2bfloat16(v1);
    __nv_bfloat16 l0 = __float2bfloat16(v0 - __bfloat162float(h0));
    __nv_bfloat16 l1 = __float2bfloat16(v1 - __bfloat162float(h1));
    h = __halves2bfloat162(h0, h1);
    l = __halves2bfloat162(l0, l1);
}

#define BM 128
#define BN 128
#define BK 64
#define STAGES 3
#define PLANE_BYTES  16384
#define STAGE_BYTES  (4 * PLANE_BYTES)
#define SMEM_TOTAL   (STAGES * STAGE_BYTES)    // 192 KB

__device__ __forceinline__ void load_plane(const __nv_bfloat16* __restrict__ g,
                                           int ld, int row0, int k0,
                                           uint32_t sbase, int t) {
#pragma unroll
    for (int i = 0; i < 4; i++) {
        int idx = i * 256 + t;
        int r = idx >> 3;
        int c = idx & 7;
        const void* gp = (const void*)(g + (size_t)(row0 + r) * ld + k0 + c * 8);
        uint32_t sp = sbase + swz(r, c);
        asm volatile("cp.async.cg.shared.global [%0], [%1], 16, 16;"
                     :: "r"(sp), "l"(gp));
    }
}
__device__ __forceinline__ void load_plane64(const __nv_bfloat16* __restrict__ g,
                                             int ld, int row0, int k0,
                                             uint32_t sbase, int t) {
#pragma unroll
    for (int i = 0; i < 2; i++) {
        int idx = i * 256 + t;
        int r = idx >> 3;
        int c = idx & 7;
        const void* gp = (const void*)(g + (size_t)(row0 + r) * ld + k0 + c * 8);
        uint32_t sp = sbase + swz(r, c);
        asm volatile("cp.async.cg.shared.global [%0], [%1], 16, 16;"
                     :: "r"(sp), "l"(gp));
    }
}

// ---------------------------------------------------------------------------
// Core 128x128 tile GEMM (device body).
// MODE 0: C fp32 out. MODE 1: Cs planes = split(acc + Csrc), SMEM-staged.
template <int MODE>
__device__ __forceinline__ void gemm_tile(
    const __nv_bfloat16* __restrict__ A1, long long planeA1, int lda1, int K1,
    const __nv_bfloat16* __restrict__ B1, long long planeB1, int ldb1,
    float* __restrict__ C, int ldc,
    __nv_bfloat16* __restrict__ Cs, long long planeCs, int ldcs,
    int m0, int n0, char* smem)
{
    const int t    = threadIdx.x;
    const int lane = t & 31;
    const int wid  = t >> 5;
    const int wm   = wid & 3;
    const int wn   = wid >> 2;
    const uint32_t sb0 = smem_u32(smem);
    const int CT = K1 >> 6;

    float acc[2][8][4];
#pragma unroll
    for (int i = 0; i < 2; i++)
#pragma unroll
        for (int j = 0; j < 8; j++)
#pragma unroll
            for (int k = 0; k < 4; k++) acc[i][j][k] = 0.f;

    int amask[2]; uint32_t aoffr[2];
#pragma unroll
    for (int mt = 0; mt < 2; mt++) {
        int ar = wm * 32 + mt * 16 + (lane & 15);
        aoffr[mt] = (uint32_t)ar * 128;
        amask[mt] = ar & 7;
    }
    const int alo = lane >> 4;
    const int gq  = lane >> 3;
    int bmask[4]; uint32_t boffr[4];
#pragma unroll
    for (int nq = 0; nq < 4; nq++) {
        int nr = wn * 64 + nq * 16 + (lane & 7) + ((gq & 2) << 2);
        boffr[nq] = (uint32_t)nr * 128;
        bmask[nq] = nr & 7;
    }
    const int blo = gq & 1;

    auto issue = [&](int cc, int stage) {
        int k0 = cc * BK;
        uint32_t sb = sb0 + stage * STAGE_BYTES;
        load_plane(A1,           lda1, m0, k0, sb,                   t);
        load_plane(A1 + planeA1, lda1, m0, k0, sb + PLANE_BYTES,     t);
        load_plane(B1,           ldb1, n0, k0, sb + 2 * PLANE_BYTES, t);
        load_plane(B1 + planeB1, ldb1, n0, k0, sb + 3 * PLANE_BYTES, t);
    };

    issue(0, 0); CP_COMMIT();
    if (CT > 1) issue(1, 1);
    CP_COMMIT();

#pragma unroll 1
    for (int cc = 0; cc < CT; cc++) {
        CP_WAIT1();
        __syncthreads();   // all warps done with stage (cc-1)%3

        const uint32_t sb = sb0 + (cc % STAGES) * STAGE_BYTES;
        const uint32_t sAh = sb, sAl = sb + PLANE_BYTES;
        const uint32_t sBh = sb + 2 * PLANE_BYTES, sBl = sb + 3 * PLANE_BYTES;

#pragma unroll
        for (int ks = 0; ks < 4; ks++) {
            const int ac = ks * 2 + alo;
            const int bc = ks * 2 + blo;
            uint32_t ah[2][4], al[2][4], bh[8][2], bl[8][2];
#pragma unroll
            for (int mt = 0; mt < 2; mt++)
                ldsm_x4(ah[mt], sAh + aoffr[mt] + (uint32_t)((ac ^ amask[mt]) << 4));
#pragma unroll
            for (int nq = 0; nq < 4; nq++) {
                uint32_t r[4];
                ldsm_x4(r, sBh + boffr[nq] + (uint32_t)((bc ^ bmask[nq]) << 4));
                bh[nq * 2][0] = r[0]; bh[nq * 2][1] = r[1];
                bh[nq * 2 + 1][0] = r[2]; bh[nq * 2 + 1][1] = r[3];
            }
#pragma unroll
            for (int mt = 0; mt < 2; mt++)
#pragma unroll
                for (int nt = 0; nt < 8; nt++) mma_bf16(acc[mt][nt], ah[mt], bh[nt]);
#pragma unroll
            for (int nq = 0; nq < 4; nq++) {
                uint32_t r[4];
                ldsm_x4(r, sBl + boffr[nq] + (uint32_t)((bc ^ bmask[nq]) << 4));
                bl[nq * 2][0] = r[0]; bl[nq * 2][1] = r[1];
                bl[nq * 2 + 1][0] = r[2]; bl[nq * 2 + 1][1] = r[3];
            }
#pragma unroll
            for (int mt = 0; mt < 2; mt++)
#pragma unroll
                for (int nt = 0; nt < 8; nt++) mma_bf16(acc[mt][nt], ah[mt], bl[nt]);
#pragma unroll
            for (int mt = 0; mt < 2; mt++)
                ldsm_x4(al[mt], sAl + aoffr[mt] + (uint32_t)((ac ^ amask[mt]) << 4));
#pragma unroll
            for (int mt = 0; mt < 2; mt++)
#pragma unroll
                for (int nt = 0; nt < 8; nt++) mma_bf16(acc[mt][nt], al[mt], bh[nt]);
        }
        int nc = cc + STAGES - 1;
        if (nc < CT) issue(nc, nc % STAGES);
        CP_COMMIT();
    }

    if (MODE == 0) {
        // fp32 out: 32B-contiguous per row-quad already — direct stores.
#pragma unroll
        for (int mt = 0; mt < 2; mt++) {
            int row = m0 + wm * 32 + mt * 16 + (lane >> 2);
#pragma unroll
            for (int nt = 0; nt < 8; nt++) {
                int col = n0 + wn * 64 + nt * 8 + (lane & 3) * 2;
                *reinterpret_cast<float2*>(C + (size_t)row * ldc + col) =
                    make_float2(acc[mt][nt][0], acc[mt][nt][1]);
                *reinterpret_cast<float2*>(C + (size_t)(row + 8) * ldc + col) =
                    make_float2(acc[mt][nt][2], acc[mt][nt][3]);
            }
        }
    } else {
        // SMEM-staged split epilogue: tile 128x128, padded stride 136 cols
        // (272B = 68 banks, 4-bank rotation/row -> conflict-free).
        __syncthreads();   // all warps done reading last stage's smem
        const int EP = 136;
        char* sHi = smem;
        char* sLo = smem + 128 * EP * 2;   // 34816B each, 69632 total < 192K
#pragma unroll
        for (int mt = 0; mt < 2; mt++) {
            int lr = wm * 32 + mt * 16 + (lane >> 2);
            int gr = m0 + lr;
#pragma unroll
            for (int nt = 0; nt < 8; nt++) {
                int lc = wn * 64 + nt * 8 + (lane & 3) * 2;
                float2 w0 = *reinterpret_cast<const float2*>(C + (size_t)gr * ldc + n0 + lc);
                float2 w1 = *reinterpret_cast<const float2*>(C + (size_t)(gr + 8) * ldc + n0 + lc);
                __nv_bfloat162 h, l;
                split2(acc[mt][nt][0] + w0.x, acc[mt][nt][1] + w0.y, h, l);
                *reinterpret_cast<__nv_bfloat162*>(sHi + (lr * EP + lc) * 2) = h;
                *reinterpret_cast<__nv_bfloat162*>(sLo + (lr * EP + lc) * 2) = l;
                split2(acc[mt][nt][2] + w1.x, acc[mt][nt][3] + w1.y, h, l);
                *reinterpret_cast<__nv_bfloat162*>(sHi + ((lr + 8) * EP + lc) * 2) = h;
                *reinterpret_cast<__nv_bfloat162*>(sLo + ((lr + 8) * EP + lc) * 2) = l;
            }
        }
        __syncthreads();
        // coalesced copy-out: 128 rows x 16 chunks of 16B per plane
#pragma unroll
        for (int i = 0; i < 8; i++) {
            int idx = i * 256 + t;
            int row = idx >> 4;
            int ch  = idx & 15;
            uint4 v = *reinterpret_cast<const uint4*>(sHi + row * (EP * 2) + ch * 16);
            *reinterpret_cast<uint4*>(Cs + (size_t)(m0 + row) * ldcs + n0 + ch * 8) = v;
            uint4 w = *reinterpret_cast<const uint4*>(sLo + row * (EP * 2) + ch * 16);
            *reinterpret_cast<uint4*>(Cs + planeCs + (size_t)(m0 + row) * ldcs + n0 + ch * 8) = w;
        }
    }
}

// plane sizes (compile-time)
#define P_X   ((long long)NTOK * HDIM)
#define P_UI  ((long long)IDIM * RPAD)   // u1s/u3s, v2ts
#define P_UH  ((long long)HDIM * RPAD)   // u2s, v1ts/v3ts
#define P_W1  ((long long)IDIM * HDIM)   // w1ps/w3ps
#define P_W2  ((long long)HDIM * IDIM)   // w2ps
#define P_H   ((long long)NTOK * IDIM)

// Merged prep: z=0 W1', z=1 W3', z=2 W2'. Grid (56, 16, 3).
__global__ __launch_bounds__(256, 1)
void prep_kernel(const __nv_bfloat16* __restrict__ u1s,
                 const __nv_bfloat16* __restrict__ u3s,
                 const __nv_bfloat16* __restrict__ u2s,
                 const __nv_bfloat16* __restrict__ v1ts,
                 const __nv_bfloat16* __restrict__ v3ts,
                 const __nv_bfloat16* __restrict__ v2ts,
                 const float* __restrict__ w1, const float* __restrict__ w3,
                 const float* __restrict__ w2,
                 __nv_bfloat16* __restrict__ w1ps,
                 __nv_bfloat16* __restrict__ w3ps,
                 __nv_bfloat16* __restrict__ w2ps)
{
    extern __shared__ char smem[];
    if (blockIdx.z == 0) {
        gemm_tile<1>(u1s, P_UI, RPAD, RPAD, v1ts, P_UH, RPAD,
                     (float*)w1, HDIM, w1ps, P_W1, HDIM,
                     blockIdx.x * BM, blockIdx.y * BN, smem);
    } else if (blockIdx.z == 1) {
        gemm_tile<1>(u3s, P_UI, RPAD, RPAD, v3ts, P_UH, RPAD,
                     (float*)w3, HDIM, w3ps, P_W1, HDIM,
                     blockIdx.x * BM, blockIdx.y * BN, smem);
    } else {
        gemm_tile<1>(u2s, P_UH, RPAD, RPAD, v2ts, P_UI, RPAD,
                     (float*)w2, IDIM, w2ps, P_W2, IDIM,
                     blockIdx.y * BM, blockIdx.x * BN, smem);
    }
}

// Down GEMM: out = h @ W2'^T (fp32 out)
__global__ __launch_bounds__(256, 1)
void down_kernel(const __nv_bfloat16* __restrict__ hs,
                 const __nv_bfloat16* __restrict__ w2ps,
                 float* __restrict__ out)
{
    extern __shared__ char smem[];
    gemm_tile<0>(hs, P_H, IDIM, IDIM, w2ps, P_W2, IDIM,
                 out, HDIM, nullptr, 0, 0,
                 blockIdx.y * BM, blockIdx.x * BN, smem);
}

// ---------------------------------------------------------------------------
// Fused gate+up: A=xs; B1=W1', B2=W3' (64 cols each); h=silu(g)*u -> planes.
#define FB1H (2 * PLANE_BYTES)
#define FB1L (FB1H + 8192)
#define FB2H (FB1L + 8192)
#define FB2L (FB2H + 8192)

__global__ __launch_bounds__(256, 1)
void fused_gateup(const __nv_bfloat16* __restrict__ xs,
                  const __nv_bfloat16* __restrict__ w1p,
                  const __nv_bfloat16* __restrict__ w3p,
                  __nv_bfloat16* __restrict__ hs)
{
    extern __shared__ char smem[];
    const int t    = threadIdx.x;
    const int lane = t & 31;
    const int wid  = t >> 5;
    const int wm   = wid & 3;
    const int wn   = wid >> 2;
    const int m0   = blockIdx.y * BM;
    const int n0   = blockIdx.x * 64;
    const uint32_t sb0 = smem_u32(smem);
    const int CT = HDIM >> 6;     // 32

    float accG[2][4][4], accU[2][4][4];
#pragma unroll
    for (int i = 0; i < 2; i++)
#pragma unroll
        for (int j = 0; j < 4; j++)
#pragma unroll
            for (int k = 0; k < 4; k++) { accG[i][j][k] = 0.f; accU[i][j][k] = 0.f; }

    int amask[2]; uint32_t aoffr[2];
#pragma unroll
    for (int mt = 0; mt < 2; mt++) {
        int ar = wm * 32 + mt * 16 + (lane & 15);
        aoffr[mt] = (uint32_t)ar * 128;
        amask[mt] = ar & 7;
    }
    const int alo = lane >> 4;
    const int gq  = lane >> 3;
    int bmask[2]; uint32_t boffr[2];
#pragma unroll
    for (int nq = 0; nq < 2; nq++) {
        int nr = wn * 32 + nq * 16 + (lane & 7) + ((gq & 2) << 2);
        boffr[nq] = (uint32_t)nr * 128;
        bmask[nq] = nr & 7;
    }
    const int blo = gq & 1;

    auto issue = [&](int cc, int stage) {
        int k0 = cc * BK;
        uint32_t sb = sb0 + stage * STAGE_BYTES;
        load_plane(xs,       HDIM, m0, k0, sb,               t);
        load_plane(xs + P_X, HDIM, m0, k0, sb + PLANE_BYTES, t);
        load_plane64(w1p,        HDIM, n0, k0, sb + FB1H, t);
        load_plane64(w1p + P_W1, HDIM, n0, k0, sb + FB1L, t);
        load_plane64(w3p,        HDIM, n0, k0, sb + FB2H, t);
        load_plane64(w3p + P_W1, HDIM, n0, k0, sb + FB2L, t);
    };

    issue(0, 0); CP_COMMIT();
    issue(1, 1); CP_COMMIT();

#pragma unroll 1
    for (int cc = 0; cc < CT; cc++) {
        CP_WAIT1();
        __syncthreads();

        const uint32_t sb = sb0 + (cc % STAGES) * STAGE_BYTES;
        const uint32_t sAh = sb, sAl = sb + PLANE_BYTES;

#pragma unroll
        for (int ks = 0; ks < 4; ks++) {
            const int ac = ks * 2 + alo;
            const int bc = ks * 2 + blo;
            uint32_t ah[2][4], al[2][4];
            uint32_t b1h[4][2], b1l[4][2], b2h[4][2], b2l[4][2];
#pragma unroll
            for (int mt = 0; mt < 2; mt++)
                ldsm_x4(ah[mt], sAh + aoffr[mt] + (uint32_t)((ac ^ amask[mt]) << 4));
#pragma unroll
            for (int nq = 0; nq < 2; nq++) {
                uint32_t bo = boffr[nq] + (uint32_t)((bc ^ bmask[nq]) << 4);
                uint32_t r[4];
                ldsm_x4(r, sb + FB1H + bo);
                b1h[nq * 2][0] = r[0]; b1h[nq * 2][1] = r[1];
                b1h[nq * 2 + 1][0] = r[2]; b1h[nq * 2 + 1][1] = r[3];
                ldsm_x4(r, sb + FB2H + bo);
                b2h[nq * 2][0] = r[0]; b2h[nq * 2][1] = r[1];
                b2h[nq * 2 + 1][0] = r[2]; b2h[nq * 2 + 1][1] = r[3];
            }
#pragma unroll
            for (int mt = 0; mt < 2; mt++)
#pragma unroll
                for (int nt = 0; nt < 4; nt++) mma_bf16(accG[mt][nt], ah[mt], b1h[nt]);
#pragma unroll
            for (int mt = 0; mt < 2; mt++)
#pragma unroll
                for (int nt = 0; nt < 4; nt++) mma_bf16(accU[mt][nt], ah[mt], b2h[nt]);
#pragma unroll
            for (int nq = 0; nq < 2; nq++) {
                uint32_t bo = boffr[nq] + (uint32_t)((bc ^ bmask[nq]) << 4);
                uint32_t r[4];
                ldsm_x4(r, sb + FB1L + bo);
                b1l[nq * 2][0] = r[0]; b1l[nq * 2][1] = r[1];
                b1l[nq * 2 + 1][0] = r[2]; b1l[nq * 2 + 1][1] = r[3];
                ldsm_x4(r, sb + FB2L + bo);
                b2l[nq * 2][0] = r[0]; b2l[nq * 2][1] = r[1];
                b2l[nq * 2 + 1][0] = r[2]; b2l[nq * 2 + 1][1] = r[3];
            }
#pragma unroll
            for (int mt = 0; mt < 2; mt++)
#pragma unroll
                for (int nt = 0; nt < 4; nt++) mma_bf16(accG[mt][nt], ah[mt], b1l[nt]);
#pragma unroll
            for (int mt = 0; mt < 2; mt++)
#pragma unroll
                for (int nt = 0; nt < 4; nt++) mma_bf16(accU[mt][nt], ah[mt], b2l[nt]);
#pragma unroll
            for (int mt = 0; mt < 2; mt++)
                ldsm_x4(al[mt], sAl + aoffr[mt] + (uint32_t)((ac ^ amask[mt]) << 4));
#pragma unroll
            for (int mt = 0; mt < 2; mt++)
#pragma unroll
                for (int nt = 0; nt < 4; nt++) mma_bf16(accG[mt][nt], al[mt], b1h[nt]);
#pragma unroll
            for (int mt = 0; mt < 2; mt++)
#pragma unroll
                for (int nt = 0; nt < 4; nt++) mma_bf16(accU[mt][nt], al[mt], b2h[nt]);
        }
        int nc = cc + STAGES - 1;
        if (nc < CT) issue(nc, nc % STAGES);
        CP_COMMIT();
    }

    // SMEM-staged epilogue: tile 128x64, padded stride 72 cols (144B = 36
    // banks, 4-bank rotation/row -> conflict-free writes and reads).
    __syncthreads();   // all warps done reading last stage's smem
    {
        const int EP = 72;
        char* sHi = smem;
        char* sLo = smem + 128 * EP * 2;   // 18432B each
#pragma unroll
        for (int mt = 0; mt < 2; mt++) {
            int lr = wm * 32 + mt * 16 + (lane >> 2);
#pragma unroll
            for (int nt = 0; nt < 4; nt++) {
                int lc = wn * 32 + nt * 8 + (lane & 3) * 2;
                __nv_bfloat162 h, l;
                split2(siluf(accG[mt][nt][0]) * accU[mt][nt][0],
                       siluf(accG[mt][nt][1]) * accU[mt][nt][1], h, l);
                *reinterpret_cast<__nv_bfloat162*>(sHi + (lr * EP + lc) * 2) = h;
                *reinterpret_cast<__nv_bfloat162*>(sLo + (lr * EP + lc) * 2) = l;
                split2(siluf(accG[mt][nt][2]) * accU[mt][nt][2],
                       siluf(accG[mt][nt][3]) * accU[mt][nt][3], h, l);
                *reinterpret_cast<__nv_bfloat162*>(sHi + ((lr + 8) * EP + lc) * 2) = h;
                *reinterpret_cast<__nv_bfloat162*>(sLo + ((lr + 8) * EP + lc) * 2) = l;
            }
        }
        __syncthreads();
        // coalesced copy-out: 128 rows x 8 chunks of 16B per plane
#pragma unroll
        for (int i = 0; i < 4; i++) {
            int idx = i * 256 + t;
            int row = idx >> 3;
            int ch  = idx & 7;
            uint4 v = *reinterpret_cast<const uint4*>(sHi + row * (EP * 2) + ch * 16);
            *reinterpret_cast<uint4*>(hs + (size_t)(m0 + row) * IDIM + n0 + ch * 8) = v;
            uint4 w = *reinterpret_cast<const uint4*>(sLo + row * (EP * 2) + ch * 16);
            *reinterpret_cast<uint4*>(hs + P_H + (size_t)(m0 + row) * IDIM + n0 + ch * 8) = w;
        }
    }
}

// ---------------------------------------------------------------------------
// x split: 8 cols/thread, float4 loads, uint4 stores. cols == dstK == HDIM.
__global__ void xsplit_kernel(const float* __restrict__ src,
                              __nv_bfloat16* __restrict__ dst, long long plane)
{
    int k0 = (blockIdx.x * blockDim.x + threadIdx.x) * 8;
    if (k0 >= HDIM) return;
    int row = blockIdx.y;
    const float* s = src + (size_t)row * HDIM + k0;
    float4 a = *reinterpret_cast<const float4*>(s);
    float4 b = *reinterpret_cast<const float4*>(s + 4);
    float v[8] = {a.x, a.y, a.z, a.w, b.x, b.y, b.z, b.w};
    __nv_bfloat162 hi[4], lo[4];
#pragma unroll
    for (int j = 0; j < 4; j++)
        split2(v[j * 2], v[j * 2 + 1], hi[j], lo[j]);
    size_t off = (size_t)row * HDIM + k0;
    *reinterpret_cast<uint4*>(dst + off)         = *reinterpret_cast<uint4*>(hi);
    *reinterpret_cast<uint4*>(dst + off + plane) = *reinterpret_cast<uint4*>(lo);
}

// Merged u-splits: z=0 u1 (IDIM rows), z=1 u3 (IDIM), z=2 u2 (HDIM rows).
__global__ void usplit_kernel(const float* __restrict__ u1,
                              const float* __restrict__ u3,
                              const float* __restrict__ u2,
                              __nv_bfloat16* __restrict__ u1s,
                              __nv_bfloat16* __restrict__ u3s,
                              __nv_bfloat16* __restrict__ u2s)
{
    int k0 = threadIdx.x * 4;
    if (k0 >= RPAD) return;
    int row = blockIdx.y;
    const float* src; __nv_bfloat16* dst; long long plane; int rows;
    if (blockIdx.z == 0)      { src = u1; dst = u1s; plane = P_UI; rows = IDIM; }
    else if (blockIdx.z == 1) { src = u3; dst = u3s; plane = P_UI; rows = IDIM; }
    else                      { src = u2; dst = u2s; plane = P_UH; rows = HDIM; }
    if (row >= rows) return;
    const float* s = src + (size_t)row * RDIM;
    __nv_bfloat16 hi[4], lo[4];
#pragma unroll
    for (int j = 0; j < 4; j++) {
        int k = k0 + j;
        float v = (k < RDIM) ? s[k] : 0.f;
        hi[j] = __float2bfloat16(v);
        lo[j] = __float2bfloat16(v - __bfloat162float(hi[j]));
    }
    size_t off = (size_t)row * RPAD + k0;
    *reinterpret_cast<__nv_bfloat162*>(dst + off)     = __halves2bfloat162(hi[0], hi[1]);
    *reinterpret_cast<__nv_bfloat162*>(dst + off + 2) = __halves2bfloat162(hi[2], hi[3]);
    *reinterpret_cast<__nv_bfloat162*>(dst + off + plane)     = __halves2bfloat162(lo[0], lo[1]);
    *reinterpret_cast<__nv_bfloat162*>(dst + off + plane + 2) = __halves2bfloat162(lo[2], lo[3]);
}

// Merged transpose-splits: z=0 v1 (C=HDIM), z=1 v3 (HDIM), z=2 v2 (IDIM).
__global__ void tsplit_kernel(const float* __restrict__ v1,
                              const float* __restrict__ v3,
                              const float* __restrict__ v2,
                              __nv_bfloat16* __restrict__ v1ts,
                              __nv_bfloat16* __restrict__ v3ts,
                              __nv_bfloat16* __restrict__ v2ts)
{
    __shared__ float sm[32][33];
    const float* src; __nv_bfloat16* dst; long long plane; int C;
    if (blockIdx.z == 0)      { src = v1; dst = v1ts; plane = P_UH; C = HDIM; }
    else if (blockIdx.z == 1) { src = v3; dst = v3ts; plane = P_UH; C = HDIM; }
    else                      { src = v2; dst = v2ts; plane = P_UI; C = IDIM; }
    int c0 = blockIdx.x * 32, r0 = blockIdx.y * 32;
    if (c0 >= C) return;
    int tx = threadIdx.x, ty = threadIdx.y;
    int r = r0 + ty;
    float v = (r < RDIM) ? src[(size_t)r * C + c0 + tx] : 0.f;
    sm[ty][tx] = v;
    __syncthreads();
    float w = sm[tx][ty];
    __nv_bfloat16 hi = __float2bfloat16(w);
    __nv_bfloat16 lo = __float2bfloat16(w - __bfloat162float(hi));
    size_t off = (size_t)(c0 + ty) * RPAD + r0 + tx;
    dst[off] = hi;
    dst[off + plane] = lo;
}

// Router logits with gw cached in SMEM (64 KB dynamic): kills the 512 MB of
// L2 traffic from every warp streaming gw. 64 blocks x 8 warps x 16 tokens.
__global__ void logits_kernel(const float* __restrict__ x,
                              const float* __restrict__ gw,
                              float* __restrict__ out)
{
    extern __shared__ float sgw[];
    const int t = threadIdx.x;
    for (int i = t; i < 8 * HDIM; i += 256)
        sgw[i] = gw[i];
    __syncthreads();
    const int warp = t >> 5, lane = t & 31;
#pragma unroll 1
    for (int i = 0; i < 16; i++) {
        int tok = (blockIdx.x * 8 + warp) * 16 + i;
        const float* xr = x + (size_t)tok * HDIM;
        float acc[8] = {0.f, 0.f, 0.f, 0.f, 0.f, 0.f, 0.f, 0.f};
        for (int k = lane; k < HDIM; k += 32) {
            float xv = xr[k];
#pragma unroll
            for (int e = 0; e < 8; e++) acc[e] += xv * sgw[e * HDIM + k];
        }
#pragma unroll
        for (int e = 0; e < 8; e++) {
            float v = acc[e];
#pragma unroll
            for (int o = 16; o; o >>= 1) v += __shfl_xor_sync(0xFFFFFFFFu, v, o);
            if (lane == 0) out[(size_t)tok * 8 + e] = v;
        }
    }
}

// ---------------------------------------------------------------------------
extern "C" void kernel_launch(void* const* d_in, const int* in_sizes, int n_in,
                              void* d_out, int out_size)
{
    const float* x  = (const float*)d_in[0];
    const float* gw = (const float*)d_in[1];
    const float* w1 = (const float*)d_in[2];
    const float* w2 = (const float*)d_in[3];
    const float* w3 = (const float*)d_in[4];
    const float* u1 = (const float*)d_in[5];
    const float* v1 = (const float*)d_in[6];
    const float* u2 = (const float*)d_in[7];
    const float* v2 = (const float*)d_in[8];
    const float* u3 = (const float*)d_in[9];
    const float* v3 = (const float*)d_in[10];

    float* out    = (float*)d_out;
    float* logits = out + (size_t)NTOK * HDIM;

    __nv_bfloat16 *xs, *u1s, *u3s, *u2s, *v1ts, *v3ts, *v2ts;
    __nv_bfloat16 *w1ps, *w3ps, *w2ps, *hs;
    cudaGetSymbolAddress((void**)&xs,   g_xs);
    cudaGetSymbolAddress((void**)&u1s,  g_u1s);
    cudaGetSymbolAddress((void**)&u3s,  g_u3s);
    cudaGetSymbolAddress((void**)&u2s,  g_u2s);
    cudaGetSymbolAddress((void**)&v1ts, g_v1ts);
    cudaGetSymbolAddress((void**)&v3ts, g_v3ts);
    cudaGetSymbolAddress((void**)&v2ts, g_v2ts);
    cudaGetSymbolAddress((void**)&w1ps, g_w1ps);
    cudaGetSymbolAddress((void**)&w3ps, g_w3ps);
    cudaGetSymbolAddress((void**)&w2ps, g_w2ps);
    cudaGetSymbolAddress((void**)&hs,   g_hs);

    cudaFuncSetAttribute(prep_kernel,   cudaFuncAttributeMaxDynamicSharedMemorySize, SMEM_TOTAL);
    cudaFuncSetAttribute(down_kernel,   cudaFuncAttributeMaxDynamicSharedMemorySize, SMEM_TOTAL);
    cudaFuncSetAttribute(fused_gateup,  cudaFuncAttributeMaxDynamicSharedMemorySize, SMEM_TOTAL);
    cudaFuncSetAttribute(logits_kernel, cudaFuncAttributeMaxDynamicSharedMemorySize, 8 * HDIM * 4);

    // ---- splits / transposes (merged launches) ----------------------------
    xsplit_kernel<<<dim3(1, NTOK), 256>>>(x, xs, P_X);
    usplit_kernel<<<dim3(1, IDIM, 3), 128>>>(u1, u3, u2, u1s, u3s, u2s);
    tsplit_kernel<<<dim3(IDIM / 32, RPAD / 32, 3), dim3(32, 32)>>>(
        v1, v3, v2, v1ts, v3ts, v2ts);

    dim3 blk(256);

    // ---- weight folding (one launch, z selects which W') ------------------
    prep_kernel<<<dim3(IDIM / BM, HDIM / BN, 3), blk, SMEM_TOTAL>>>(
        u1s, u3s, u2s, v1ts, v3ts, v2ts, w1, w3, w2, w1ps, w3ps, w2ps);

    // ---- fused gate/up + silu -> h planes ---------------------------------
    fused_gateup<<<dim3(IDIM / 64, NTOK / BM), blk, SMEM_TOTAL>>>(
        xs, w1ps, w3ps, hs);

    // ---- out = h @ W2'^T --------------------------------------------------
    down_kernel<<<dim3(HDIM / BN, NTOK / BM), blk, SMEM_TOTAL>>>(hs, w2ps, out);

    // ---- router logits (SMEM-cached gw) -----------------------------------
    logits_kernel<<<64, 256, 8 * HDIM * 4>>>(x, gw, logits);
}

// round 13
// speedup vs baseline: 1.0181x; 1.0181x over previous
#include <cuda_runtime.h>
#include <cuda_bf16.h>
#include <cstdint>
#include <cstddef>

// ---------------------------------------------------------------------------
// Merge_MixtralSparseMoeBlock — weight-folded, bf16 hi/lo split (3 passes):
//   W1' = w1 + u1@v1 ; W3' = w3 + u3@v3 ; W2' = w2 + u2@v2   (one prep launch)
//   gate = x@W1'^T ; up = x@W3'^T  (fused, shared A tiles)
//   h = silu(gate)*up  (fused epilogue -> bf16 hi/lo planes)
//   out = h@W2'^T ; logits = x@gate_w^T
// R13: R8 GEMM core (best) + vectorized xsplit + high-parallelism SMEM logits.
// ---------------------------------------------------------------------------

#define NTOK 8192
#define HDIM 2048
#define IDIM 7168
#define RDIM 398
#define RPAD 448

// ---------------- device scratch -------------------------------------------
__device__ __align__(16) __nv_bfloat16 g_xs  [2ull * NTOK * HDIM];
__device__ __align__(16) __nv_bfloat16 g_u1s [2ull * IDIM * RPAD];
__device__ __align__(16) __nv_bfloat16 g_u3s [2ull * IDIM * RPAD];
__device__ __align__(16) __nv_bfloat16 g_u2s [2ull * HDIM * RPAD];
__device__ __align__(16) __nv_bfloat16 g_v1ts[2ull * HDIM * RPAD];
__device__ __align__(16) __nv_bfloat16 g_v3ts[2ull * HDIM * RPAD];
__device__ __align__(16) __nv_bfloat16 g_v2ts[2ull * IDIM * RPAD];
__device__ __align__(16) __nv_bfloat16 g_w1ps[2ull * IDIM * HDIM];
__device__ __align__(16) __nv_bfloat16 g_w3ps[2ull * IDIM * HDIM];
__device__ __align__(16) __nv_bfloat16 g_w2ps[2ull * HDIM * IDIM];
__device__ __align__(16) __nv_bfloat16 g_hs  [2ull * NTOK * IDIM];

// ---------------- PTX helpers ----------------------------------------------
__device__ __forceinline__ uint32_t smem_u32(const void* p) {
    uint32_t a;
    asm("{ .reg .u64 t; cvta.to.shared.u64 t, %1; cvt.u32.u64 %0, t; }"
        : "=r"(a) : "l"(p));
    return a;
}
__device__ __forceinline__ void ldsm_x4(uint32_t* r, uint32_t addr) {
    asm volatile("ldmatrix.sync.aligned.m8n8.x4.shared.b16 {%0,%1,%2,%3}, [%4];"
                 : "=r"(r[0]), "=r"(r[1]), "=r"(r[2]), "=r"(r[3]) : "r"(addr));
}
__device__ __forceinline__ void mma_bf16(float* d, const uint32_t* a, const uint32_t* b) {
    asm volatile("mma.sync.aligned.m16n8k16.row.col.f32.bf16.bf16.f32 "
                 "{%0,%1,%2,%3}, {%4,%5,%6,%7}, {%8,%9}, {%0,%1,%2,%3};"
                 : "+f"(d[0]), "+f"(d[1]), "+f"(d[2]), "+f"(d[3])
                 : "r"(a[0]), "r"(a[1]), "r"(a[2]), "r"(a[3]),
                   "r"(b[0]), "r"(b[1]));
}
#define CP_COMMIT() asm volatile("cp.async.commit_group;" ::: "memory")
#define CP_WAIT1()  asm volatile("cp.async.wait_group 1;" ::: "memory")

// BK=64 rows are 128B (8 x 16B chunks); chunk' = c ^ (r&7) is conflict-free.
__device__ __forceinline__ uint32_t swz(int r, int c) {
    return (uint32_t)(r * 128 + ((c ^ (r & 7)) << 4));
}
__device__ __forceinline__ float siluf(float x) { return x / (1.f + __expf(-x)); }

// pack two fp32 into hi/lo bf16x2 words
__device__ __forceinline__ void split2(float v0, float v1,
                                       __nv_bfloat162& h, __nv_bfloat162& l) {
    __nv_bfloat16 h0 = __float2bfloat16(v0), h1 = __float2bfloat16(v1);
    __nv_bfloat16 l0 = __float2bfloat16(v0 - __bfloat162float(h0));
    __nv_bfloat16 l1 = __float2bfloat16(v1 - __bfloat162float(h1));
    h = __halves2bfloat162(h0, h1);
    l = __halves2bfloat162(l0, l1);
}

#define BM 128
#define BN 128
#define BK 64
#define STAGES 3
#define PLANE_BYTES  16384
#define STAGE_BYTES  (4 * PLANE_BYTES)
#define SMEM_TOTAL   (STAGES * STAGE_BYTES)    // 192 KB

__device__ __forceinline__ void load_plane(const __nv_bfloat16* __restrict__ g,
                                           int ld, int row0, int k0,
                                           uint32_t sbase, int t) {
#pragma unroll
    for (int i = 0; i < 4; i++) {
        int idx = i * 256 + t;
        int r = idx >> 3;
        int c = idx & 7;
        const void* gp = (const void*)(g + (size_t)(row0 + r) * ld + k0 + c * 8);
        uint32_t sp = sbase + swz(r, c);
        asm volatile("cp.async.cg.shared.global [%0], [%1], 16, 16;"
                     :: "r"(sp), "l"(gp));
    }
}
__device__ __forceinline__ void load_plane64(const __nv_bfloat16* __restrict__ g,
                                             int ld, int row0, int k0,
                                             uint32_t sbase, int t) {
#pragma unroll
    for (int i = 0; i < 2; i++) {
        int idx = i * 256 + t;
        int r = idx >> 3;
        int c = idx & 7;
        const void* gp = (const void*)(g + (size_t)(row0 + r) * ld + k0 + c * 8);
        uint32_t sp = sbase + swz(r, c);
        asm volatile("cp.async.cg.shared.global [%0], [%1], 16, 16;"
                     :: "r"(sp), "l"(gp));
    }
}

// ---------------------------------------------------------------------------
// Core 128x128 tile GEMM (device body).
// MODE 0: C fp32 out. MODE 1: Cs planes = split(acc + Csrc), SMEM-staged.
template <int MODE>
__device__ __forceinline__ void gemm_tile(
    const __nv_bfloat16* __restrict__ A1, long long planeA1, int lda1, int K1,
    const __nv_bfloat16* __restrict__ B1, long long planeB1, int ldb1,
    float* __restrict__ C, int ldc,
    __nv_bfloat16* __restrict__ Cs, long long planeCs, int ldcs,
    int m0, int n0, char* smem)
{
    const int t    = threadIdx.x;
    const int lane = t & 31;
    const int wid  = t >> 5;
    const int wm   = wid & 3;
    const int wn   = wid >> 2;
    const uint32_t sb0 = smem_u32(smem);
    const int CT = K1 >> 6;

    float acc[2][8][4];
#pragma unroll
    for (int i = 0; i < 2; i++)
#pragma unroll
        for (int j = 0; j < 8; j++)
#pragma unroll
            for (int k = 0; k < 4; k++) acc[i][j][k] = 0.f;

    int amask[2]; uint32_t aoffr[2];
#pragma unroll
    for (int mt = 0; mt < 2; mt++) {
        int ar = wm * 32 + mt * 16 + (lane & 15);
        aoffr[mt] = (uint32_t)ar * 128;
        amask[mt] = ar & 7;
    }
    const int alo = lane >> 4;
    const int gq  = lane >> 3;
    int bmask[4]; uint32_t boffr[4];
#pragma unroll
    for (int nq = 0; nq < 4; nq++) {
        int nr = wn * 64 + nq * 16 + (lane & 7) + ((gq & 2) << 2);
        boffr[nq] = (uint32_t)nr * 128;
        bmask[nq] = nr & 7;
    }
    const int blo = gq & 1;

    auto issue = [&](int cc, int stage) {
        int k0 = cc * BK;
        uint32_t sb = sb0 + stage * STAGE_BYTES;
        load_plane(A1,           lda1, m0, k0, sb,                   t);
        load_plane(A1 + planeA1, lda1, m0, k0, sb + PLANE_BYTES,     t);
        load_plane(B1,           ldb1, n0, k0, sb + 2 * PLANE_BYTES, t);
        load_plane(B1 + planeB1, ldb1, n0, k0, sb + 3 * PLANE_BYTES, t);
    };

    issue(0, 0); CP_COMMIT();
    if (CT > 1) issue(1, 1);
    CP_COMMIT();

#pragma unroll 1
    for (int cc = 0; cc < CT; cc++) {
        CP_WAIT1();
        __syncthreads();   // all warps done with stage (cc-1)%3

        const uint32_t sb = sb0 + (cc % STAGES) * STAGE_BYTES;
        const uint32_t sAh = sb, sAl = sb + PLANE_BYTES;
        const uint32_t sBh = sb + 2 * PLANE_BYTES, sBl = sb + 3 * PLANE_BYTES;

#pragma unroll
        for (int ks = 0; ks < 4; ks++) {
            const int ac = ks * 2 + alo;
            const int bc = ks * 2 + blo;
            uint32_t ah[2][4], al[2][4], bh[8][2], bl[8][2];
#pragma unroll
            for (int mt = 0; mt < 2; mt++)
                ldsm_x4(ah[mt], sAh + aoffr[mt] + (uint32_t)((ac ^ amask[mt]) << 4));
#pragma unroll
            for (int nq = 0; nq < 4; nq++) {
                uint32_t r[4];
                ldsm_x4(r, sBh + boffr[nq] + (uint32_t)((bc ^ bmask[nq]) << 4));
                bh[nq * 2][0] = r[0]; bh[nq * 2][1] = r[1];
                bh[nq * 2 + 1][0] = r[2]; bh[nq * 2 + 1][1] = r[3];
            }
#pragma unroll
            for (int mt = 0; mt < 2; mt++)
#pragma unroll
                for (int nt = 0; nt < 8; nt++) mma_bf16(acc[mt][nt], ah[mt], bh[nt]);
#pragma unroll
            for (int nq = 0; nq < 4; nq++) {
                uint32_t r[4];
                ldsm_x4(r, sBl + boffr[nq] + (uint32_t)((bc ^ bmask[nq]) << 4));
                bl[nq * 2][0] = r[0]; bl[nq * 2][1] = r[1];
                bl[nq * 2 + 1][0] = r[2]; bl[nq * 2 + 1][1] = r[3];
            }
#pragma unroll
            for (int mt = 0; mt < 2; mt++)
#pragma unroll
                for (int nt = 0; nt < 8; nt++) mma_bf16(acc[mt][nt], ah[mt], bl[nt]);
#pragma unroll
            for (int mt = 0; mt < 2; mt++)
                ldsm_x4(al[mt], sAl + aoffr[mt] + (uint32_t)((ac ^ amask[mt]) << 4));
#pragma unroll
            for (int mt = 0; mt < 2; mt++)
#pragma unroll
                for (int nt = 0; nt < 8; nt++) mma_bf16(acc[mt][nt], al[mt], bh[nt]);
        }
        int nc = cc + STAGES - 1;
        if (nc < CT) issue(nc, nc % STAGES);
        CP_COMMIT();
    }

    if (MODE == 0) {
        // fp32 out: 32B-contiguous per row-quad already — direct stores.
#pragma unroll
        for (int mt = 0; mt < 2; mt++) {
            int row = m0 + wm * 32 + mt * 16 + (lane >> 2);
#pragma unroll
            for (int nt = 0; nt < 8; nt++) {
                int col = n0 + wn * 64 + nt * 8 + (lane & 3) * 2;
                *reinterpret_cast<float2*>(C + (size_t)row * ldc + col) =
                    make_float2(acc[mt][nt][0], acc[mt][nt][1]);
                *reinterpret_cast<float2*>(C + (size_t)(row + 8) * ldc + col) =
                    make_float2(acc[mt][nt][2], acc[mt][nt][3]);
            }
        }
    } else {
        // SMEM-staged split epilogue: tile 128x128, padded stride 136 cols
        // (272B = 68 banks, 4-bank rotation/row -> conflict-free).
        __syncthreads();   // all warps done reading last stage's smem
        const int EP = 136;
        char* sHi = smem;
        char* sLo = smem + 128 * EP * 2;   // 34816B each, 69632 total < 192K
#pragma unroll
        for (int mt = 0; mt < 2; mt++) {
            int lr = wm * 32 + mt * 16 + (lane >> 2);
            int gr = m0 + lr;
#pragma unroll
            for (int nt = 0; nt < 8; nt++) {
                int lc = wn * 64 + nt * 8 + (lane & 3) * 2;
                float2 w0 = *reinterpret_cast<const float2*>(C + (size_t)gr * ldc + n0 + lc);
                float2 w1 = *reinterpret_cast<const float2*>(C + (size_t)(gr + 8) * ldc + n0 + lc);
                __nv_bfloat162 h, l;
                split2(acc[mt][nt][0] + w0.x, acc[mt][nt][1] + w0.y, h, l);
                *reinterpret_cast<__nv_bfloat162*>(sHi + (lr * EP + lc) * 2) = h;
                *reinterpret_cast<__nv_bfloat162*>(sLo + (lr * EP + lc) * 2) = l;
                split2(acc[mt][nt][2] + w1.x, acc[mt][nt][3] + w1.y, h, l);
                *reinterpret_cast<__nv_bfloat162*>(sHi + ((lr + 8) * EP + lc) * 2) = h;
                *reinterpret_cast<__nv_bfloat162*>(sLo + ((lr + 8) * EP + lc) * 2) = l;
            }
        }
        __syncthreads();
        // coalesced copy-out: 128 rows x 16 chunks of 16B per plane
#pragma unroll
        for (int i = 0; i < 8; i++) {
            int idx = i * 256 + t;
            int row = idx >> 4;
            int ch  = idx & 15;
            uint4 v = *reinterpret_cast<const uint4*>(sHi + row * (EP * 2) + ch * 16);
            *reinterpret_cast<uint4*>(Cs + (size_t)(m0 + row) * ldcs + n0 + ch * 8) = v;
            uint4 w = *reinterpret_cast<const uint4*>(sLo + row * (EP * 2) + ch * 16);
            *reinterpret_cast<uint4*>(Cs + planeCs + (size_t)(m0 + row) * ldcs + n0 + ch * 8) = w;
        }
    }
}

// plane sizes (compile-time)
#define P_X   ((long long)NTOK * HDIM)
#define P_UI  ((long long)IDIM * RPAD)   // u1s/u3s, v2ts
#define P_UH  ((long long)HDIM * RPAD)   // u2s, v1ts/v3ts
#define P_W1  ((long long)IDIM * HDIM)   // w1ps/w3ps
#define P_W2  ((long long)HDIM * IDIM)   // w2ps
#define P_H   ((long long)NTOK * IDIM)

// Merged prep: z=0 W1', z=1 W3', z=2 W2'. Grid (56, 16, 3).
__global__ __launch_bounds__(256, 1)
void prep_kernel(const __nv_bfloat16* __restrict__ u1s,
                 const __nv_bfloat16* __restrict__ u3s,
                 const __nv_bfloat16* __restrict__ u2s,
                 const __nv_bfloat16* __restrict__ v1ts,
                 const __nv_bfloat16* __restrict__ v3ts,
                 const __nv_bfloat16* __restrict__ v2ts,
                 const float* __restrict__ w1, const float* __restrict__ w3,
                 const float* __restrict__ w2,
                 __nv_bfloat16* __restrict__ w1ps,
                 __nv_bfloat16* __restrict__ w3ps,
                 __nv_bfloat16* __restrict__ w2ps)
{
    extern __shared__ char smem[];
    if (blockIdx.z == 0) {
        gemm_tile<1>(u1s, P_UI, RPAD, RPAD, v1ts, P_UH, RPAD,
                     (float*)w1, HDIM, w1ps, P_W1, HDIM,
                     blockIdx.x * BM, blockIdx.y * BN, smem);
    } else if (blockIdx.z == 1) {
        gemm_tile<1>(u3s, P_UI, RPAD, RPAD, v3ts, P_UH, RPAD,
                     (float*)w3, HDIM, w3ps, P_W1, HDIM,
                     blockIdx.x * BM, blockIdx.y * BN, smem);
    } else {
        gemm_tile<1>(u2s, P_UH, RPAD, RPAD, v2ts, P_UI, RPAD,
                     (float*)w2, IDIM, w2ps, P_W2, IDIM,
                     blockIdx.y * BM, blockIdx.x * BN, smem);
    }
}

// Down GEMM: out = h @ W2'^T (fp32 out)
__global__ __launch_bounds__(256, 1)
void down_kernel(const __nv_bfloat16* __restrict__ hs,
                 const __nv_bfloat16* __restrict__ w2ps,
                 float* __restrict__ out)
{
    extern __shared__ char smem[];
    gemm_tile<0>(hs, P_H, IDIM, IDIM, w2ps, P_W2, IDIM,
                 out, HDIM, nullptr, 0, 0,
                 blockIdx.y * BM, blockIdx.x * BN, smem);
}

// ---------------------------------------------------------------------------
// Fused gate+up: A=xs; B1=W1', B2=W3' (64 cols each); h=silu(g)*u -> planes.
#define FB1H (2 * PLANE_BYTES)
#define FB1L (FB1H + 8192)
#define FB2H (FB1L + 8192)
#define FB2L (FB2H + 8192)

__global__ __launch_bounds__(256, 1)
void fused_gateup(const __nv_bfloat16* __restrict__ xs,
                  const __nv_bfloat16* __restrict__ w1p,
                  const __nv_bfloat16* __restrict__ w3p,
                  __nv_bfloat16* __restrict__ hs)
{
    extern __shared__ char smem[];
    const int t    = threadIdx.x;
    const int lane = t & 31;
    const int wid  = t >> 5;
    const int wm   = wid & 3;
    const int wn   = wid >> 2;
    const int m0   = blockIdx.y * BM;
    const int n0   = blockIdx.x * 64;
    const uint32_t sb0 = smem_u32(smem);
    const int CT = HDIM >> 6;     // 32

    float accG[2][4][4], accU[2][4][4];
#pragma unroll
    for (int i = 0; i < 2; i++)
#pragma unroll
        for (int j = 0; j < 4; j++)
#pragma unroll
            for (int k = 0; k < 4; k++) { accG[i][j][k] = 0.f; accU[i][j][k] = 0.f; }

    int amask[2]; uint32_t aoffr[2];
#pragma unroll
    for (int mt = 0; mt < 2; mt++) {
        int ar = wm * 32 + mt * 16 + (lane & 15);
        aoffr[mt] = (uint32_t)ar * 128;
        amask[mt] = ar & 7;
    }
    const int alo = lane >> 4;
    const int gq  = lane >> 3;
    int bmask[2]; uint32_t boffr[2];
#pragma unroll
    for (int nq = 0; nq < 2; nq++) {
        int nr = wn * 32 + nq * 16 + (lane & 7) + ((gq & 2) << 2);
        boffr[nq] = (uint32_t)nr * 128;
        bmask[nq] = nr & 7;
    }
    const int blo = gq & 1;

    auto issue = [&](int cc, int stage) {
        int k0 = cc * BK;
        uint32_t sb = sb0 + stage * STAGE_BYTES;
        load_plane(xs,       HDIM, m0, k0, sb,               t);
        load_plane(xs + P_X, HDIM, m0, k0, sb + PLANE_BYTES, t);
        load_plane64(w1p,        HDIM, n0, k0, sb + FB1H, t);
        load_plane64(w1p + P_W1, HDIM, n0, k0, sb + FB1L, t);
        load_plane64(w3p,        HDIM, n0, k0, sb + FB2H, t);
        load_plane64(w3p + P_W1, HDIM, n0, k0, sb + FB2L, t);
    };

    issue(0, 0); CP_COMMIT();
    issue(1, 1); CP_COMMIT();

#pragma unroll 1
    for (int cc = 0; cc < CT; cc++) {
        CP_WAIT1();
        __syncthreads();

        const uint32_t sb = sb0 + (cc % STAGES) * STAGE_BYTES;
        const uint32_t sAh = sb, sAl = sb + PLANE_BYTES;

#pragma unroll
        for (int ks = 0; ks < 4; ks++) {
            const int ac = ks * 2 + alo;
            const int bc = ks * 2 + blo;
            uint32_t ah[2][4], al[2][4];
            uint32_t b1h[4][2], b1l[4][2], b2h[4][2], b2l[4][2];
#pragma unroll
            for (int mt = 0; mt < 2; mt++)
                ldsm_x4(ah[mt], sAh + aoffr[mt] + (uint32_t)((ac ^ amask[mt]) << 4));
#pragma unroll
            for (int nq = 0; nq < 2; nq++) {
                uint32_t bo = boffr[nq] + (uint32_t)((bc ^ bmask[nq]) << 4);
                uint32_t r[4];
                ldsm_x4(r, sb + FB1H + bo);
                b1h[nq * 2][0] = r[0]; b1h[nq * 2][1] = r[1];
                b1h[nq * 2 + 1][0] = r[2]; b1h[nq * 2 + 1][1] = r[3];
                ldsm_x4(r, sb + FB2H + bo);
                b2h[nq * 2][0] = r[0]; b2h[nq * 2][1] = r[1];
                b2h[nq * 2 + 1][0] = r[2]; b2h[nq * 2 + 1][1] = r[3];
            }
#pragma unroll
            for (int mt = 0; mt < 2; mt++)
#pragma unroll
                for (int nt = 0; nt < 4; nt++) mma_bf16(accG[mt][nt], ah[mt], b1h[nt]);
#pragma unroll
            for (int mt = 0; mt < 2; mt++)
#pragma unroll
                for (int nt = 0; nt < 4; nt++) mma_bf16(accU[mt][nt], ah[mt], b2h[nt]);
#pragma unroll
            for (int nq = 0; nq < 2; nq++) {
                uint32_t bo = boffr[nq] + (uint32_t)((bc ^ bmask[nq]) << 4);
                uint32_t r[4];
                ldsm_x4(r, sb + FB1L + bo);
                b1l[nq * 2][0] = r[0]; b1l[nq * 2][1] = r[1];
                b1l[nq * 2 + 1][0] = r[2]; b1l[nq * 2 + 1][1] = r[3];
                ldsm_x4(r, sb + FB2L + bo);
                b2l[nq * 2][0] = r[0]; b2l[nq * 2][1] = r[1];
                b2l[nq * 2 + 1][0] = r[2]; b2l[nq * 2 + 1][1] = r[3];
            }
#pragma unroll
            for (int mt = 0; mt < 2; mt++)
#pragma unroll
                for (int nt = 0; nt < 4; nt++) mma_bf16(accG[mt][nt], ah[mt], b1l[nt]);
#pragma unroll
            for (int mt = 0; mt < 2; mt++)
#pragma unroll
                for (int nt = 0; nt < 4; nt++) mma_bf16(accU[mt][nt], ah[mt], b2l[nt]);
#pragma unroll
            for (int mt = 0; mt < 2; mt++)
                ldsm_x4(al[mt], sAl + aoffr[mt] + (uint32_t)((ac ^ amask[mt]) << 4));
#pragma unroll
            for (int mt = 0; mt < 2; mt++)
#pragma unroll
                for (int nt = 0; nt < 4; nt++) mma_bf16(accG[mt][nt], al[mt], b1h[nt]);
#pragma unroll
            for (int mt = 0; mt < 2; mt++)
#pragma unroll
                for (int nt = 0; nt < 4; nt++) mma_bf16(accU[mt][nt], al[mt], b2h[nt]);
        }
        int nc = cc + STAGES - 1;
        if (nc < CT) issue(nc, nc % STAGES);
        CP_COMMIT();
    }

    // SMEM-staged epilogue: tile 128x64, padded stride 72 cols (144B = 36
    // banks, 4-bank rotation/row -> conflict-free writes and reads).
    __syncthreads();   // all warps done reading last stage's smem
    {
        const int EP = 72;
        char* sHi = smem;
        char* sLo = smem + 128 * EP * 2;   // 18432B each
#pragma unroll
        for (int mt = 0; mt < 2; mt++) {
            int lr = wm * 32 + mt * 16 + (lane >> 2);
#pragma unroll
            for (int nt = 0; nt < 4; nt++) {
                int lc = wn * 32 + nt * 8 + (lane & 3) * 2;
                __nv_bfloat162 h, l;
                split2(siluf(accG[mt][nt][0]) * accU[mt][nt][0],
                       siluf(accG[mt][nt][1]) * accU[mt][nt][1], h, l);
                *reinterpret_cast<__nv_bfloat162*>(sHi + (lr * EP + lc) * 2) = h;
                *reinterpret_cast<__nv_bfloat162*>(sLo + (lr * EP + lc) * 2) = l;
                split2(siluf(accG[mt][nt][2]) * accU[mt][nt][2],
                       siluf(accG[mt][nt][3]) * accU[mt][nt][3], h, l);
                *reinterpret_cast<__nv_bfloat162*>(sHi + ((lr + 8) * EP + lc) * 2) = h;
                *reinterpret_cast<__nv_bfloat162*>(sLo + ((lr + 8) * EP + lc) * 2) = l;
            }
        }
        __syncthreads();
        // coalesced copy-out: 128 rows x 8 chunks of 16B per plane
#pragma unroll
        for (int i = 0; i < 4; i++) {
            int idx = i * 256 + t;
            int row = idx >> 3;
            int ch  = idx & 7;
            uint4 v = *reinterpret_cast<const uint4*>(sHi + row * (EP * 2) + ch * 16);
            *reinterpret_cast<uint4*>(hs + (size_t)(m0 + row) * IDIM + n0 + ch * 8) = v;
            uint4 w = *reinterpret_cast<const uint4*>(sLo + row * (EP * 2) + ch * 16);
            *reinterpret_cast<uint4*>(hs + P_H + (size_t)(m0 + row) * IDIM + n0 + ch * 8) = w;
        }
    }
}

// ---------------------------------------------------------------------------
// x split: 8 cols/thread, float4 loads, uint4 stores.
__global__ void xsplit_kernel(const float* __restrict__ src,
                              __nv_bfloat16* __restrict__ dst, long long plane)
{
    int k0 = (blockIdx.x * blockDim.x + threadIdx.x) * 8;
    if (k0 >= HDIM) return;
    int row = blockIdx.y;
    const float* s = src + (size_t)row * HDIM + k0;
    float4 a = *reinterpret_cast<const float4*>(s);
    float4 b = *reinterpret_cast<const float4*>(s + 4);
    float v[8] = {a.x, a.y, a.z, a.w, b.x, b.y, b.z, b.w};
    __nv_bfloat162 hi[4], lo[4];
#pragma unroll
    for (int j = 0; j < 4; j++)
        split2(v[j * 2], v[j * 2 + 1], hi[j], lo[j]);
    size_t off = (size_t)row * HDIM + k0;
    *reinterpret_cast<uint4*>(dst + off)         = *reinterpret_cast<uint4*>(hi);
    *reinterpret_cast<uint4*>(dst + off + plane) = *reinterpret_cast<uint4*>(lo);
}

// Merged u-splits: z=0 u1 (IDIM rows), z=1 u3 (IDIM), z=2 u2 (HDIM rows).
__global__ void usplit_kernel(const float* __restrict__ u1,
                              const float* __restrict__ u3,
                              const float* __restrict__ u2,
                              __nv_bfloat16* __restrict__ u1s,
                              __nv_bfloat16* __restrict__ u3s,
                              __nv_bfloat16* __restrict__ u2s)
{
    int k0 = threadIdx.x * 4;
    if (k0 >= RPAD) return;
    int row = blockIdx.y;
    const float* src; __nv_bfloat16* dst; long long plane; int rows;
    if (blockIdx.z == 0)      { src = u1; dst = u1s; plane = P_UI; rows = IDIM; }
    else if (blockIdx.z == 1) { src = u3; dst = u3s; plane = P_UI; rows = IDIM; }
    else                      { src = u2; dst = u2s; plane = P_UH; rows = HDIM; }
    if (row >= rows) return;
    const float* s = src + (size_t)row * RDIM;
    __nv_bfloat16 hi[4], lo[4];
#pragma unroll
    for (int j = 0; j < 4; j++) {
        int k = k0 + j;
        float v = (k < RDIM) ? s[k] : 0.f;
        hi[j] = __float2bfloat16(v);
        lo[j] = __float2bfloat16(v - __bfloat162float(hi[j]));
    }
    size_t off = (size_t)row * RPAD + k0;
    *reinterpret_cast<__nv_bfloat162*>(dst + off)     = __halves2bfloat162(hi[0], hi[1]);
    *reinterpret_cast<__nv_bfloat162*>(dst + off + 2) = __halves2bfloat162(hi[2], hi[3]);
    *reinterpret_cast<__nv_bfloat162*>(dst + off + plane)     = __halves2bfloat162(lo[0], lo[1]);
    *reinterpret_cast<__nv_bfloat162*>(dst + off + plane + 2) = __halves2bfloat162(lo[2], lo[3]);
}

// Merged transpose-splits: z=0 v1 (C=HDIM), z=1 v3 (HDIM), z=2 v2 (IDIM).
__global__ void tsplit_kernel(const float* __restrict__ v1,
                              const float* __restrict__ v3,
                              const float* __restrict__ v2,
                              __nv_bfloat16* __restrict__ v1ts,
                              __nv_bfloat16* __restrict__ v3ts,
                              __nv_bfloat16* __restrict__ v2ts)
{
    __shared__ float sm[32][33];
    const float* src; __nv_bfloat16* dst; long long plane; int C;
    if (blockIdx.z == 0)      { src = v1; dst = v1ts; plane = P_UH; C = HDIM; }
    else if (blockIdx.z == 1) { src = v3; dst = v3ts; plane = P_UH; C = HDIM; }
    else                      { src = v2; dst = v2ts; plane = P_UI; C = IDIM; }
    int c0 = blockIdx.x * 32, r0 = blockIdx.y * 32;
    if (c0 >= C) return;
    int tx = threadIdx.x, ty = threadIdx.y;
    int r = r0 + ty;
    float v = (r < RDIM) ? src[(size_t)r * C + c0 + tx] : 0.f;
    sm[ty][tx] = v;
    __syncthreads();
    float w = sm[tx][ty];
    __nv_bfloat16 hi = __float2bfloat16(w);
    __nv_bfloat16 lo = __float2bfloat16(w - __bfloat162float(hi));
    size_t off = (size_t)(c0 + ty) * RPAD + r0 + tx;
    dst[off] = hi;
    dst[off + plane] = lo;
}

// Router logits, SMEM-cached gw with high parallelism: 512 blocks x 8 warps,
// 2 tokens per warp (same accumulation order as the original -> bit-identical).
__global__ void logits_kernel(const float* __restrict__ x,
                              const float* __restrict__ gw,
                              float* __restrict__ out)
{
    extern __shared__ float sgw[];
    const int t = threadIdx.x;
    for (int i = t; i < 8 * HDIM; i += 256)
        sgw[i] = gw[i];
    __syncthreads();
    const int warp = t >> 5, lane = t & 31;
#pragma unroll 1
    for (int i = 0; i < 2; i++) {
        int tok = (blockIdx.x * 8 + warp) * 2 + i;
        const float* xr = x + (size_t)tok * HDIM;
        float acc[8] = {0.f, 0.f, 0.f, 0.f, 0.f, 0.f, 0.f, 0.f};
        for (int k = lane; k < HDIM; k += 32) {
            float xv = xr[k];
#pragma unroll
            for (int e = 0; e < 8; e++) acc[e] += xv * sgw[e * HDIM + k];
        }
#pragma unroll
        for (int e = 0; e < 8; e++) {
            float v = acc[e];
#pragma unroll
            for (int o = 16; o; o >>= 1) v += __shfl_xor_sync(0xFFFFFFFFu, v, o);
            if (lane == 0) out[(size_t)tok * 8 + e] = v;
        }
    }
}

// ---------------------------------------------------------------------------
extern "C" void kernel_launch(void* const* d_in, const int* in_sizes, int n_in,
                              void* d_out, int out_size)
{
    const float* x  = (const float*)d_in[0];
    const float* gw = (const float*)d_in[1];
    const float* w1 = (const float*)d_in[2];
    const float* w2 = (const float*)d_in[3];
    const float* w3 = (const float*)d_in[4];
    const float* u1 = (const float*)d_in[5];
    const float* v1 = (const float*)d_in[6];
    const float* u2 = (const float*)d_in[7];
    const float* v2 = (const float*)d_in[8];
    const float* u3 = (const float*)d_in[9];
    const float* v3 = (const float*)d_in[10];

    float* out    = (float*)d_out;
    float* logits = out + (size_t)NTOK * HDIM;

    __nv_bfloat16 *xs, *u1s, *u3s, *u2s, *v1ts, *v3ts, *v2ts;
    __nv_bfloat16 *w1ps, *w3ps, *w2ps, *hs;
    cudaGetSymbolAddress((void**)&xs,   g_xs);
    cudaGetSymbolAddress((void**)&u1s,  g_u1s);
    cudaGetSymbolAddress((void**)&u3s,  g_u3s);
    cudaGetSymbolAddress((void**)&u2s,  g_u2s);
    cudaGetSymbolAddress((void**)&v1ts, g_v1ts);
    cudaGetSymbolAddress((void**)&v3ts, g_v3ts);
    cudaGetSymbolAddress((void**)&v2ts, g_v2ts);
    cudaGetSymbolAddress((void**)&w1ps, g_w1ps);
    cudaGetSymbolAddress((void**)&w3ps, g_w3ps);
    cudaGetSymbolAddress((void**)&w2ps, g_w2ps);
    cudaGetSymbolAddress((void**)&hs,   g_hs);

    cudaFuncSetAttribute(prep_kernel,   cudaFuncAttributeMaxDynamicSharedMemorySize, SMEM_TOTAL);
    cudaFuncSetAttribute(down_kernel,   cudaFuncAttributeMaxDynamicSharedMemorySize, SMEM_TOTAL);
    cudaFuncSetAttribute(fused_gateup,  cudaFuncAttributeMaxDynamicSharedMemorySize, SMEM_TOTAL);
    cudaFuncSetAttribute(logits_kernel, cudaFuncAttributeMaxDynamicSharedMemorySize, 8 * HDIM * 4);

    // ---- splits / transposes (merged launches) ----------------------------
    xsplit_kernel<<<dim3(1, NTOK), 256>>>(x, xs, P_X);
    usplit_kernel<<<dim3(1, IDIM, 3), 128>>>(u1, u3, u2, u1s, u3s, u2s);
    tsplit_kernel<<<dim3(IDIM / 32, RPAD / 32, 3), dim3(32, 32)>>>(
        v1, v3, v2, v1ts, v3ts, v2ts);

    dim3 blk(256);

    // ---- weight folding (one launch, z selects which W') ------------------
    prep_kernel<<<dim3(IDIM / BM, HDIM / BN, 3), blk, SMEM_TOTAL>>>(
        u1s, u3s, u2s, v1ts, v3ts, v2ts, w1, w3, w2, w1ps, w3ps, w2ps);

    // ---- fused gate/up + silu -> h planes ---------------------------------
    fused_gateup<<<dim3(IDIM / 64, NTOK / BM), blk, SMEM_TOTAL>>>(
        xs, w1ps, w3ps, hs);

    // ---- out = h @ W2'^T --------------------------------------------------
    down_kernel<<<dim3(HDIM / BN, NTOK / BM), blk, SMEM_TOTAL>>>(hs, w2ps, out);

    // ---- router logits (SMEM-cached gw, 512 blocks) -----------------------
    logits_kernel<<<512, 256, 8 * HDIM * 4>>>(x, gw, logits);
}

// round 14
// speedup vs baseline: 1.0190x; 1.0009x over previous
#include <cuda_runtime.h>
#include <cuda_bf16.h>
#include <cstdint>
#include <cstddef>

// ---------------------------------------------------------------------------
// Merge_MixtralSparseMoeBlock — weight-folded, bf16 hi/lo split (3 passes):
//   W1' = w1 + u1@v1 ; W3' = w3 + u3@v3 ; W2' = w2 + u2@v2   (prep, 2 CTA/SM)
//   gate = x@W1'^T ; up = x@W3'^T  (fused, shared A tiles)
//   h = silu(gate)*up  (fused epilogue -> bf16 hi/lo planes)
//   out = h@W2'^T ; logits = x@gate_w^T
// R14: R8/R13 core unchanged; prep rewritten as 128x64/BK=32 tiles with
//      72 KB SMEM -> 2 CTAs/SM to hide short-K fill/drain.
// ---------------------------------------------------------------------------

#define NTOK 8192
#define HDIM 2048
#define IDIM 7168
#define RDIM 398
#define RPAD 448

// ---------------- device scratch -------------------------------------------
__device__ __align__(16) __nv_bfloat16 g_xs  [2ull * NTOK * HDIM];
__device__ __align__(16) __nv_bfloat16 g_u1s [2ull * IDIM * RPAD];
__device__ __align__(16) __nv_bfloat16 g_u3s [2ull * IDIM * RPAD];
__device__ __align__(16) __nv_bfloat16 g_u2s [2ull * HDIM * RPAD];
__device__ __align__(16) __nv_bfloat16 g_v1ts[2ull * HDIM * RPAD];
__device__ __align__(16) __nv_bfloat16 g_v3ts[2ull * HDIM * RPAD];
__device__ __align__(16) __nv_bfloat16 g_v2ts[2ull * IDIM * RPAD];
__device__ __align__(16) __nv_bfloat16 g_w1ps[2ull * IDIM * HDIM];
__device__ __align__(16) __nv_bfloat16 g_w3ps[2ull * IDIM * HDIM];
__device__ __align__(16) __nv_bfloat16 g_w2ps[2ull * HDIM * IDIM];
__device__ __align__(16) __nv_bfloat16 g_hs  [2ull * NTOK * IDIM];

// ---------------- PTX helpers ----------------------------------------------
__device__ __forceinline__ uint32_t smem_u32(const void* p) {
    uint32_t a;
    asm("{ .reg .u64 t; cvta.to.shared.u64 t, %1; cvt.u32.u64 %0, t; }"
        : "=r"(a) : "l"(p));
    return a;
}
__device__ __forceinline__ void ldsm_x4(uint32_t* r, uint32_t addr) {
    asm volatile("ldmatrix.sync.aligned.m8n8.x4.shared.b16 {%0,%1,%2,%3}, [%4];"
                 : "=r"(r[0]), "=r"(r[1]), "=r"(r[2]), "=r"(r[3]) : "r"(addr));
}
__device__ __forceinline__ void mma_bf16(float* d, const uint32_t* a, const uint32_t* b) {
    asm volatile("mma.sync.aligned.m16n8k16.row.col.f32.bf16.bf16.f32 "
                 "{%0,%1,%2,%3}, {%4,%5,%6,%7}, {%8,%9}, {%0,%1,%2,%3};"
                 : "+f"(d[0]), "+f"(d[1]), "+f"(d[2]), "+f"(d[3])
                 : "r"(a[0]), "r"(a[1]), "r"(a[2]), "r"(a[3]),
                   "r"(b[0]), "r"(b[1]));
}
#define CP_COMMIT() asm volatile("cp.async.commit_group;" ::: "memory")
#define CP_WAIT1()  asm volatile("cp.async.wait_group 1;" ::: "memory")

// BK=64: 128B rows, chunk' = c ^ (r&7).
__device__ __forceinline__ uint32_t swz(int r, int c) {
    return (uint32_t)(r * 128 + ((c ^ (r & 7)) << 4));
}
// BK=32: 64B rows, chunk' = c ^ ((r>>1)&3)  (validated R3 layout).
__device__ __forceinline__ uint32_t swz32(int r, int c) {
    return (uint32_t)(r * 64 + ((c ^ ((r >> 1) & 3)) << 4));
}
__device__ __forceinline__ float siluf(float x) { return x / (1.f + __expf(-x)); }

__device__ __forceinline__ void split2(float v0, float v1,
                                       __nv_bfloat162& h, __nv_bfloat162& l) {
    __nv_bfloat16 h0 = __float2bfloat16(v0), h1 = __float2bfloat16(v1);
    __nv_bfloat16 l0 = __float2bfloat16(v0 - __bfloat162float(h0));
    __nv_bfloat16 l1 = __float2bfloat16(v1 - __bfloat162float(h1));
    h = __halves2bfloat162(h0, h1);
    l = __halves2bfloat162(l0, l1);
}

#define BM 128
#define BN 128
#define BK 64
#define STAGES 3
#define PLANE_BYTES  16384
#define STAGE_BYTES  (4 * PLANE_BYTES)
#define SMEM_TOTAL   (STAGES * STAGE_BYTES)    // 192 KB

__device__ __forceinline__ void load_plane(const __nv_bfloat16* __restrict__ g,
                                           int ld, int row0, int k0,
                                           uint32_t sbase, int t) {
#pragma unroll
    for (int i = 0; i < 4; i++) {
        int idx = i * 256 + t;
        int r = idx >> 3;
        int c = idx & 7;
        const void* gp = (const void*)(g + (size_t)(row0 + r) * ld + k0 + c * 8);
        uint32_t sp = sbase + swz(r, c);
        asm volatile("cp.async.cg.shared.global [%0], [%1], 16, 16;"
                     :: "r"(sp), "l"(gp));
    }
}
__device__ __forceinline__ void load_plane64(const __nv_bfloat16* __restrict__ g,
                                             int ld, int row0, int k0,
                                             uint32_t sbase, int t) {
#pragma unroll
    for (int i = 0; i < 2; i++) {
        int idx = i * 256 + t;
        int r = idx >> 3;
        int c = idx & 7;
        const void* gp = (const void*)(g + (size_t)(row0 + r) * ld + k0 + c * 8);
        uint32_t sp = sbase + swz(r, c);
        asm volatile("cp.async.cg.shared.global [%0], [%1], 16, 16;"
                     :: "r"(sp), "l"(gp));
    }
}
// BK=32 loaders (64B rows)
__device__ __forceinline__ void load32_128(const __nv_bfloat16* __restrict__ g,
                                           int ld, int row0, int k0,
                                           uint32_t sbase, int t) {
#pragma unroll
    for (int i = 0; i < 2; i++) {
        int idx = i * 256 + t;
        int r = idx >> 2;
        int c = idx & 3;
        const void* gp = (const void*)(g + (size_t)(row0 + r) * ld + k0 + c * 8);
        uint32_t sp = sbase + swz32(r, c);
        asm volatile("cp.async.cg.shared.global [%0], [%1], 16, 16;"
                     :: "r"(sp), "l"(gp));
    }
}
__device__ __forceinline__ void load32_64(const __nv_bfloat16* __restrict__ g,
                                          int ld, int row0, int k0,
                                          uint32_t sbase, int t) {
    int r = t >> 2;
    int c = t & 3;
    const void* gp = (const void*)(g + (size_t)(row0 + r) * ld + k0 + c * 8);
    uint32_t sp = sbase + swz32(r, c);
    asm volatile("cp.async.cg.shared.global [%0], [%1], 16, 16;"
                 :: "r"(sp), "l"(gp));
}

// plane sizes (compile-time)
#define P_X   ((long long)NTOK * HDIM)
#define P_UI  ((long long)IDIM * RPAD)
#define P_UH  ((long long)HDIM * RPAD)
#define P_W1  ((long long)IDIM * HDIM)
#define P_W2  ((long long)HDIM * IDIM)
#define P_H   ((long long)NTOK * IDIM)

// ---------------------------------------------------------------------------
// Down GEMM core: 128x128, BK=64 (unchanged R8).
__global__ __launch_bounds__(256, 1)
void down_kernel(const __nv_bfloat16* __restrict__ hs,
                 const __nv_bfloat16* __restrict__ w2ps,
                 float* __restrict__ out)
{
    extern __shared__ char smem[];
    const int t    = threadIdx.x;
    const int lane = t & 31;
    const int wid  = t >> 5;
    const int wm   = wid & 3;
    const int wn   = wid >> 2;
    const int m0   = blockIdx.y * BM;
    const int n0   = blockIdx.x * BN;
    const uint32_t sb0 = smem_u32(smem);
    const int CT = IDIM >> 6;

    float acc[2][8][4];
#pragma unroll
    for (int i = 0; i < 2; i++)
#pragma unroll
        for (int j = 0; j < 8; j++)
#pragma unroll
            for (int k = 0; k < 4; k++) acc[i][j][k] = 0.f;

    int amask[2]; uint32_t aoffr[2];
#pragma unroll
    for (int mt = 0; mt < 2; mt++) {
        int ar = wm * 32 + mt * 16 + (lane & 15);
        aoffr[mt] = (uint32_t)ar * 128;
        amask[mt] = ar & 7;
    }
    const int alo = lane >> 4;
    const int gq  = lane >> 3;
    int bmask[4]; uint32_t boffr[4];
#pragma unroll
    for (int nq = 0; nq < 4; nq++) {
        int nr = wn * 64 + nq * 16 + (lane & 7) + ((gq & 2) << 2);
        boffr[nq] = (uint32_t)nr * 128;
        bmask[nq] = nr & 7;
    }
    const int blo = gq & 1;

    auto issue = [&](int cc, int stage) {
        int k0 = cc * BK;
        uint32_t sb = sb0 + stage * STAGE_BYTES;
        load_plane(hs,          IDIM, m0, k0, sb,                   t);
        load_plane(hs + P_H,    IDIM, m0, k0, sb + PLANE_BYTES,     t);
        load_plane(w2ps,        IDIM, n0, k0, sb + 2 * PLANE_BYTES, t);
        load_plane(w2ps + P_W2, IDIM, n0, k0, sb + 3 * PLANE_BYTES, t);
    };

    issue(0, 0); CP_COMMIT();
    issue(1, 1); CP_COMMIT();

#pragma unroll 1
    for (int cc = 0; cc < CT; cc++) {
        CP_WAIT1();
        __syncthreads();

        const uint32_t sb = sb0 + (cc % STAGES) * STAGE_BYTES;
        const uint32_t sAh = sb, sAl = sb + PLANE_BYTES;
        const uint32_t sBh = sb + 2 * PLANE_BYTES, sBl = sb + 3 * PLANE_BYTES;

#pragma unroll
        for (int ks = 0; ks < 4; ks++) {
            const int ac = ks * 2 + alo;
            const int bc = ks * 2 + blo;
            uint32_t ah[2][4], al[2][4], bh[8][2], bl[8][2];
#pragma unroll
            for (int mt = 0; mt < 2; mt++)
                ldsm_x4(ah[mt], sAh + aoffr[mt] + (uint32_t)((ac ^ amask[mt]) << 4));
#pragma unroll
            for (int nq = 0; nq < 4; nq++) {
                uint32_t r[4];
                ldsm_x4(r, sBh + boffr[nq] + (uint32_t)((bc ^ bmask[nq]) << 4));
                bh[nq * 2][0] = r[0]; bh[nq * 2][1] = r[1];
                bh[nq * 2 + 1][0] = r[2]; bh[nq * 2 + 1][1] = r[3];
            }
#pragma unroll
            for (int mt = 0; mt < 2; mt++)
#pragma unroll
                for (int nt = 0; nt < 8; nt++) mma_bf16(acc[mt][nt], ah[mt], bh[nt]);
#pragma unroll
            for (int nq = 0; nq < 4; nq++) {
                uint32_t r[4];
                ldsm_x4(r, sBl + boffr[nq] + (uint32_t)((bc ^ bmask[nq]) << 4));
                bl[nq * 2][0] = r[0]; bl[nq * 2][1] = r[1];
                bl[nq * 2 + 1][0] = r[2]; bl[nq * 2 + 1][1] = r[3];
            }
#pragma unroll
            for (int mt = 0; mt < 2; mt++)
#pragma unroll
                for (int nt = 0; nt < 8; nt++) mma_bf16(acc[mt][nt], ah[mt], bl[nt]);
#pragma unroll
            for (int mt = 0; mt < 2; mt++)
                ldsm_x4(al[mt], sAl + aoffr[mt] + (uint32_t)((ac ^ amask[mt]) << 4));
#pragma unroll
            for (int mt = 0; mt < 2; mt++)
#pragma unroll
                for (int nt = 0; nt < 8; nt++) mma_bf16(acc[mt][nt], al[mt], bh[nt]);
        }
        int nc = cc + STAGES - 1;
        if (nc < CT) issue(nc, nc % STAGES);
        CP_COMMIT();
    }

#pragma unroll
    for (int mt = 0; mt < 2; mt++) {
        int row = m0 + wm * 32 + mt * 16 + (lane >> 2);
#pragma unroll
        for (int nt = 0; nt < 8; nt++) {
            int col = n0 + wn * 64 + nt * 8 + (lane & 3) * 2;
            *reinterpret_cast<float2*>(out + (size_t)row * HDIM + col) =
                make_float2(acc[mt][nt][0], acc[mt][nt][1]);
            *reinterpret_cast<float2*>(out + (size_t)(row + 8) * HDIM + col) =
                make_float2(acc[mt][nt][2], acc[mt][nt][3]);
        }
    }
}

// ---------------------------------------------------------------------------
// Prep: W' = w + u@v^T, 128x64 tiles, BK=32, 72 KB smem -> 2 CTAs/SM.
#define PB_A32 8192                       // 128 x 32 bf16
#define PB_B32 4096                       // 64 x 32 bf16
#define STG32  (2 * PB_A32 + 2 * PB_B32)  // 24576
#define SMEM32 (3 * STG32)                // 73728

__global__ __launch_bounds__(256, 2)
void prep_kernel(const __nv_bfloat16* __restrict__ u1s,
                 const __nv_bfloat16* __restrict__ u3s,
                 const __nv_bfloat16* __restrict__ u2s,
                 const __nv_bfloat16* __restrict__ v1ts,
                 const __nv_bfloat16* __restrict__ v3ts,
                 const __nv_bfloat16* __restrict__ v2ts,
                 const float* __restrict__ w1, const float* __restrict__ w3,
                 const float* __restrict__ w2,
                 __nv_bfloat16* __restrict__ w1ps,
                 __nv_bfloat16* __restrict__ w3ps,
                 __nv_bfloat16* __restrict__ w2ps)
{
    extern __shared__ char smem[];
    const int t    = threadIdx.x;
    const int lane = t & 31;
    const int wid  = t >> 5;
    const int wm   = wid & 3;
    const int wn   = wid >> 2;
    const int z    = blockIdx.z;

    int m0, n0;
    if (z < 2) { m0 = blockIdx.x * 128; n0 = blockIdx.y * 64; }
    else { int lt = blockIdx.y * 56 + blockIdx.x;
           m0 = (lt / 112) * 128; n0 = (lt % 112) * 64; }

    const __nv_bfloat16 *A, *B; long long pA, pB;
    const float* C; int ldc; __nv_bfloat16* Cs; long long pCs;
    if (z == 0)      { A = u1s; pA = P_UI; B = v1ts; pB = P_UH;
                       C = w1; ldc = HDIM; Cs = w1ps; pCs = P_W1; }
    else if (z == 1) { A = u3s; pA = P_UI; B = v3ts; pB = P_UH;
                       C = w3; ldc = HDIM; Cs = w3ps; pCs = P_W1; }
    else             { A = u2s; pA = P_UH; B = v2ts; pB = P_UI;
                       C = w2; ldc = IDIM; Cs = w2ps; pCs = P_W2; }

    const uint32_t sb0 = smem_u32(smem);
    const int CT = RPAD / 32;   // 14

    float acc[2][4][4];
#pragma unroll
    for (int i = 0; i < 2; i++)
#pragma unroll
        for (int j = 0; j < 4; j++)
#pragma unroll
            for (int k = 0; k < 4; k++) acc[i][j][k] = 0.f;

    int amask[2]; uint32_t aoffr[2];
#pragma unroll
    for (int mt = 0; mt < 2; mt++) {
        int ar = wm * 32 + mt * 16 + (lane & 15);
        aoffr[mt] = (uint32_t)ar * 64;
        amask[mt] = (ar >> 1) & 3;
    }
    const int alo = lane >> 4;
    const int gq  = lane >> 3;
    int bmask[2]; uint32_t boffr[2];
#pragma unroll
    for (int nq = 0; nq < 2; nq++) {
        int nr = wn * 32 + nq * 16 + (lane & 7) + ((gq & 2) << 2);
        boffr[nq] = (uint32_t)nr * 64;
        bmask[nq] = (nr >> 1) & 3;
    }
    const int blo = gq & 1;

    auto issue = [&](int cc, int stage) {
        int k0 = cc * 32;
        uint32_t sb = sb0 + stage * STG32;
        load32_128(A,      RPAD, m0, k0, sb,           t);
        load32_128(A + pA, RPAD, m0, k0, sb + PB_A32,  t);
        load32_64(B,       RPAD, n0, k0, sb + 2 * PB_A32,          t);
        load32_64(B + pB,  RPAD, n0, k0, sb + 2 * PB_A32 + PB_B32, t);
    };

    issue(0, 0); CP_COMMIT();
    issue(1, 1); CP_COMMIT();

#pragma unroll 1
    for (int cc = 0; cc < CT; cc++) {
        CP_WAIT1();
        __syncthreads();

        const uint32_t sb = sb0 + (cc % 3) * STG32;
        const uint32_t sAh = sb, sAl = sb + PB_A32;
        const uint32_t sBh = sb + 2 * PB_A32, sBl = sBh + PB_B32;

#pragma unroll
        for (int ks = 0; ks < 2; ks++) {
            const int ac = ks * 2 + alo;
            const int bc = ks * 2 + blo;
            uint32_t ah[2][4], al[2][4], bh[4][2], bl[4][2];
#pragma unroll
            for (int mt = 0; mt < 2; mt++)
                ldsm_x4(ah[mt], sAh + aoffr[mt] + (uint32_t)((ac ^ amask[mt]) << 4));
#pragma unroll
            for (int nq = 0; nq < 2; nq++) {
                uint32_t r[4];
                ldsm_x4(r, sBh + boffr[nq] + (uint32_t)((bc ^ bmask[nq]) << 4));
                bh[nq * 2][0] = r[0]; bh[nq * 2][1] = r[1];
                bh[nq * 2 + 1][0] = r[2]; bh[nq * 2 + 1][1] = r[3];
            }
#pragma unroll
            for (int mt = 0; mt < 2; mt++)
#pragma unroll
                for (int nt = 0; nt < 4; nt++) mma_bf16(acc[mt][nt], ah[mt], bh[nt]);
#pragma unroll
            for (int nq = 0; nq < 2; nq++) {
                uint32_t r[4];
                ldsm_x4(r, sBl + boffr[nq] + (uint32_t)((bc ^ bmask[nq]) << 4));
                bl[nq * 2][0] = r[0]; bl[nq * 2][1] = r[1];
                bl[nq * 2 + 1][0] = r[2]; bl[nq * 2 + 1][1] = r[3];
            }
#pragma unroll
            for (int mt = 0; mt < 2; mt++)
#pragma unroll
                for (int nt = 0; nt < 4; nt++) mma_bf16(acc[mt][nt], ah[mt], bl[nt]);
#pragma unroll
            for (int mt = 0; mt < 2; mt++)
                ldsm_x4(al[mt], sAl + aoffr[mt] + (uint32_t)((ac ^ amask[mt]) << 4));
#pragma unroll
            for (int mt = 0; mt < 2; mt++)
#pragma unroll
                for (int nt = 0; nt < 4; nt++) mma_bf16(acc[mt][nt], al[mt], bh[nt]);
        }
        int nc = cc + 2;
        if (nc < CT) issue(nc, nc % 3);
        CP_COMMIT();
    }

    // staged split epilogue (EP=72 layout, validated in fused_gateup) + C add
    __syncthreads();
    {
        const int EP = 72;
        char* sHi = smem;
        char* sLo = smem + 128 * EP * 2;   // 36864 total <= 73728
#pragma unroll
        for (int mt = 0; mt < 2; mt++) {
            int lr = wm * 32 + mt * 16 + (lane >> 2);
            int gr = m0 + lr;
#pragma unroll
            for (int nt = 0; nt < 4; nt++) {
                int lc = wn * 32 + nt * 8 + (lane & 3) * 2;
                float2 c0 = *reinterpret_cast<const float2*>(C + (size_t)gr * ldc + n0 + lc);
                float2 c1 = *reinterpret_cast<const float2*>(C + (size_t)(gr + 8) * ldc + n0 + lc);
                __nv_bfloat162 h, l;
                split2(acc[mt][nt][0] + c0.x, acc[mt][nt][1] + c0.y, h, l);
                *reinterpret_cast<__nv_bfloat162*>(sHi + (lr * EP + lc) * 2) = h;
                *reinterpret_cast<__nv_bfloat162*>(sLo + (lr * EP + lc) * 2) = l;
                split2(acc[mt][nt][2] + c1.x, acc[mt][nt][3] + c1.y, h, l);
                *reinterpret_cast<__nv_bfloat162*>(sHi + ((lr + 8) * EP + lc) * 2) = h;
                *reinterpret_cast<__nv_bfloat162*>(sLo + ((lr + 8) * EP + lc) * 2) = l;
            }
        }
        __syncthreads();
#pragma unroll
        for (int i = 0; i < 4; i++) {
            int idx = i * 256 + t;
            int row = idx >> 3;
            int ch  = idx & 7;
            uint4 v = *reinterpret_cast<const uint4*>(sHi + row * (EP * 2) + ch * 16);
            *reinterpret_cast<uint4*>(Cs + (size_t)(m0 + row) * ldc + n0 + ch * 8) = v;
            uint4 w = *reinterpret_cast<const uint4*>(sLo + row * (EP * 2) + ch * 16);
            *reinterpret_cast<uint4*>(Cs + pCs + (size_t)(m0 + row) * ldc + n0 + ch * 8) = w;
        }
    }
}

// ---------------------------------------------------------------------------
// Fused gate+up (unchanged R8).
#define FB1H (2 * PLANE_BYTES)
#define FB1L (FB1H + 8192)
#define FB2H (FB1L + 8192)
#define FB2L (FB2H + 8192)

__global__ __launch_bounds__(256, 1)
void fused_gateup(const __nv_bfloat16* __restrict__ xs,
                  const __nv_bfloat16* __restrict__ w1p,
                  const __nv_bfloat16* __restrict__ w3p,
                  __nv_bfloat16* __restrict__ hs)
{
    extern __shared__ char smem[];
    const int t    = threadIdx.x;
    const int lane = t & 31;
    const int wid  = t >> 5;
    const int wm   = wid & 3;
    const int wn   = wid >> 2;
    const int m0   = blockIdx.y * BM;
    const int n0   = blockIdx.x * 64;
    const uint32_t sb0 = smem_u32(smem);
    const int CT = HDIM >> 6;

    float accG[2][4][4], accU[2][4][4];
#pragma unroll
    for (int i = 0; i < 2; i++)
#pragma unroll
        for (int j = 0; j < 4; j++)
#pragma unroll
            for (int k = 0; k < 4; k++) { accG[i][j][k] = 0.f; accU[i][j][k] = 0.f; }

    int amask[2]; uint32_t aoffr[2];
#pragma unroll
    for (int mt = 0; mt < 2; mt++) {
        int ar = wm * 32 + mt * 16 + (lane & 15);
        aoffr[mt] = (uint32_t)ar * 128;
        amask[mt] = ar & 7;
    }
    const int alo = lane >> 4;
    const int gq  = lane >> 3;
    int bmask[2]; uint32_t boffr[2];
#pragma unroll
    for (int nq = 0; nq < 2; nq++) {
        int nr = wn * 32 + nq * 16 + (lane & 7) + ((gq & 2) << 2);
        boffr[nq] = (uint32_t)nr * 128;
        bmask[nq] = nr & 7;
    }
    const int blo = gq & 1;

    auto issue = [&](int cc, int stage) {
        int k0 = cc * BK;
        uint32_t sb = sb0 + stage * STAGE_BYTES;
        load_plane(xs,       HDIM, m0, k0, sb,               t);
        load_plane(xs + P_X, HDIM, m0, k0, sb + PLANE_BYTES, t);
        load_plane64(w1p,        HDIM, n0, k0, sb + FB1H, t);
        load_plane64(w1p + P_W1, HDIM, n0, k0, sb + FB1L, t);
        load_plane64(w3p,        HDIM, n0, k0, sb + FB2H, t);
        load_plane64(w3p + P_W1, HDIM, n0, k0, sb + FB2L, t);
    };

    issue(0, 0); CP_COMMIT();
    issue(1, 1); CP_COMMIT();

#pragma unroll 1
    for (int cc = 0; cc < CT; cc++) {
        CP_WAIT1();
        __syncthreads();

        const uint32_t sb = sb0 + (cc % STAGES) * STAGE_BYTES;
        const uint32_t sAh = sb, sAl = sb + PLANE_BYTES;

#pragma unroll
        for (int ks = 0; ks < 4; ks++) {
            const int ac = ks * 2 + alo;
            const int bc = ks * 2 + blo;
            uint32_t ah[2][4], al[2][4];
            uint32_t b1h[4][2], b1l[4][2], b2h[4][2], b2l[4][2];
#pragma unroll
            for (int mt = 0; mt < 2; mt++)
                ldsm_x4(ah[mt], sAh + aoffr[mt] + (uint32_t)((ac ^ amask[mt]) << 4));
#pragma unroll
            for (int nq = 0; nq < 2; nq++) {
                uint32_t bo = boffr[nq] + (uint32_t)((bc ^ bmask[nq]) << 4);
                uint32_t r[4];
                ldsm_x4(r, sb + FB1H + bo);
                b1h[nq * 2][0] = r[0]; b1h[nq * 2][1] = r[1];
                b1h[nq * 2 + 1][0] = r[2]; b1h[nq * 2 + 1][1] = r[3];
                ldsm_x4(r, sb + FB2H + bo);
                b2h[nq * 2][0] = r[0]; b2h[nq * 2][1] = r[1];
                b2h[nq * 2 + 1][0] = r[2]; b2h[nq * 2 + 1][1] = r[3];
            }
#pragma unroll
            for (int mt = 0; mt < 2; mt++)
#pragma unroll
                for (int nt = 0; nt < 4; nt++) mma_bf16(accG[mt][nt], ah[mt], b1h[nt]);
#pragma unroll
            for (int mt = 0; mt < 2; mt++)
#pragma unroll
                for (int nt = 0; nt < 4; nt++) mma_bf16(accU[mt][nt], ah[mt], b2h[nt]);
#pragma unroll
            for (int nq = 0; nq < 2; nq++) {
                uint32_t bo = boffr[nq] + (uint32_t)((bc ^ bmask[nq]) << 4);
                uint32_t r[4];
                ldsm_x4(r, sb + FB1L + bo);
                b1l[nq * 2][0] = r[0]; b1l[nq * 2][1] = r[1];
                b1l[nq * 2 + 1][0] = r[2]; b1l[nq * 2 + 1][1] = r[3];
                ldsm_x4(r, sb + FB2L + bo);
                b2l[nq * 2][0] = r[0]; b2l[nq * 2][1] = r[1];
                b2l[nq * 2 + 1][0] = r[2]; b2l[nq * 2 + 1][1] = r[3];
            }
#pragma unroll
            for (int mt = 0; mt < 2; mt++)
#pragma unroll
                for (int nt = 0; nt < 4; nt++) mma_bf16(accG[mt][nt], ah[mt], b1l[nt]);
#pragma unroll
            for (int mt = 0; mt < 2; mt++)
#pragma unroll
                for (int nt = 0; nt < 4; nt++) mma_bf16(accU[mt][nt], ah[mt], b2l[nt]);
#pragma unroll
            for (int mt = 0; mt < 2; mt++)
                ldsm_x4(al[mt], sAl + aoffr[mt] + (uint32_t)((ac ^ amask[mt]) << 4));
#pragma unroll
            for (int mt = 0; mt < 2; mt++)
#pragma unroll
                for (int nt = 0; nt < 4; nt++) mma_bf16(accG[mt][nt], al[mt], b1h[nt]);
#pragma unroll
            for (int mt = 0; mt < 2; mt++)
#pragma unroll
                for (int nt = 0; nt < 4; nt++) mma_bf16(accU[mt][nt], al[mt], b2h[nt]);
        }
        int nc = cc + STAGES - 1;
        if (nc < CT) issue(nc, nc % STAGES);
        CP_COMMIT();
    }

    __syncthreads();
    {
        const int EP = 72;
        char* sHi = smem;
        char* sLo = smem + 128 * EP * 2;
#pragma unroll
        for (int mt = 0; mt < 2; mt++) {
            int lr = wm * 32 + mt * 16 + (lane >> 2);
#pragma unroll
            for (int nt = 0; nt < 4; nt++) {
                int lc = wn * 32 + nt * 8 + (lane & 3) * 2;
                __nv_bfloat162 h, l;
                split2(siluf(accG[mt][nt][0]) * accU[mt][nt][0],
                       siluf(accG[mt][nt][1]) * accU[mt][nt][1], h, l);
                *reinterpret_cast<__nv_bfloat162*>(sHi + (lr * EP + lc) * 2) = h;
                *reinterpret_cast<__nv_bfloat162*>(sLo + (lr * EP + lc) * 2) = l;
                split2(siluf(accG[mt][nt][2]) * accU[mt][nt][2],
                       siluf(accG[mt][nt][3]) * accU[mt][nt][3], h, l);
                *reinterpret_cast<__nv_bfloat162*>(sHi + ((lr + 8) * EP + lc) * 2) = h;
                *reinterpret_cast<__nv_bfloat162*>(sLo + ((lr + 8) * EP + lc) * 2) = l;
            }
        }
        __syncthreads();
#pragma unroll
        for (int i = 0; i < 4; i++) {
            int idx = i * 256 + t;
            int row = idx >> 3;
            int ch  = idx & 7;
            uint4 v = *reinterpret_cast<const uint4*>(sHi + row * (EP * 2) + ch * 16);
            *reinterpret_cast<uint4*>(hs + (size_t)(m0 + row) * IDIM + n0 + ch * 8) = v;
            uint4 w = *reinterpret_cast<const uint4*>(sLo + row * (EP * 2) + ch * 16);
            *reinterpret_cast<uint4*>(hs + P_H + (size_t)(m0 + row) * IDIM + n0 + ch * 8) = w;
        }
    }
}

// ---------------------------------------------------------------------------
__global__ void xsplit_kernel(const float* __restrict__ src,
                              __nv_bfloat16* __restrict__ dst, long long plane)
{
    int k0 = (blockIdx.x * blockDim.x + threadIdx.x) * 8;
    if (k0 >= HDIM) return;
    int row = blockIdx.y;
    const float* s = src + (size_t)row * HDIM + k0;
    float4 a = *reinterpret_cast<const float4*>(s);
    float4 b = *reinterpret_cast<const float4*>(s + 4);
    float v[8] = {a.x, a.y, a.z, a.w, b.x, b.y, b.z, b.w};
    __nv_bfloat162 hi[4], lo[4];
#pragma unroll
    for (int j = 0; j < 4; j++)
        split2(v[j * 2], v[j * 2 + 1], hi[j], lo[j]);
    size_t off = (size_t)row * HDIM + k0;
    *reinterpret_cast<uint4*>(dst + off)         = *reinterpret_cast<uint4*>(hi);
    *reinterpret_cast<uint4*>(dst + off + plane) = *reinterpret_cast<uint4*>(lo);
}

__global__ void usplit_kernel(const float* __restrict__ u1,
                              const float* __restrict__ u3,
                              const float* __restrict__ u2,
                              __nv_bfloat16* __restrict__ u1s,
                              __nv_bfloat16* __restrict__ u3s,
                              __nv_bfloat16* __restrict__ u2s)
{
    int k0 = threadIdx.x * 4;
    if (k0 >= RPAD) return;
    int row = blockIdx.y;
    const float* src; __nv_bfloat16* dst; long long plane; int rows;
    if (blockIdx.z == 0)      { src = u1; dst = u1s; plane = P_UI; rows = IDIM; }
    else if (blockIdx.z == 1) { src = u3; dst = u3s; plane = P_UI; rows = IDIM; }
    else                      { src = u2; dst = u2s; plane = P_UH; rows = HDIM; }
    if (row >= rows) return;
    const float* s = src + (size_t)row * RDIM;
    __nv_bfloat16 hi[4], lo[4];
#pragma unroll
    for (int j = 0; j < 4; j++) {
        int k = k0 + j;
        float v = (k < RDIM) ? s[k] : 0.f;
        hi[j] = __float2bfloat16(v);
        lo[j] = __float2bfloat16(v - __bfloat162float(hi[j]));
    }
    size_t off = (size_t)row * RPAD + k0;
    *reinterpret_cast<__nv_bfloat162*>(dst + off)     = __halves2bfloat162(hi[0], hi[1]);
    *reinterpret_cast<__nv_bfloat162*>(dst + off + 2) = __halves2bfloat162(hi[2], hi[3]);
    *reinterpret_cast<__nv_bfloat162*>(dst + off + plane)     = __halves2bfloat162(lo[0], lo[1]);
    *reinterpret_cast<__nv_bfloat162*>(dst + off + plane + 2) = __halves2bfloat162(lo[2], lo[3]);
}

__global__ void tsplit_kernel(const float* __restrict__ v1,
                              const float* __restrict__ v3,
                              const float* __restrict__ v2,
                              __nv_bfloat16* __restrict__ v1ts,
                              __nv_bfloat16* __restrict__ v3ts,
                              __nv_bfloat16* __restrict__ v2ts)
{
    __shared__ float sm[32][33];
    const float* src; __nv_bfloat16* dst; long long plane; int C;
    if (blockIdx.z == 0)      { src = v1; dst = v1ts; plane = P_UH; C = HDIM; }
    else if (blockIdx.z == 1) { src = v3; dst = v3ts; plane = P_UH; C = HDIM; }
    else                      { src = v2; dst = v2ts; plane = P_UI; C = IDIM; }
    int c0 = blockIdx.x * 32, r0 = blockIdx.y * 32;
    if (c0 >= C) return;
    int tx = threadIdx.x, ty = threadIdx.y;
    int r = r0 + ty;
    float v = (r < RDIM) ? src[(size_t)r * C + c0 + tx] : 0.f;
    sm[ty][tx] = v;
    __syncthreads();
    float w = sm[tx][ty];
    __nv_bfloat16 hi = __float2bfloat16(w);
    __nv_bfloat16 lo = __float2bfloat16(w - __bfloat162float(hi));
    size_t off = (size_t)(c0 + ty) * RPAD + r0 + tx;
    dst[off] = hi;
    dst[off + plane] = lo;
}

__global__ void logits_kernel(const float* __restrict__ x,
                              const float* __restrict__ gw,
                              float* __restrict__ out)
{
    extern __shared__ float sgw[];
    const int t = threadIdx.x;
    for (int i = t; i < 8 * HDIM; i += 256)
        sgw[i] = gw[i];
    __syncthreads();
    const int warp = t >> 5, lane = t & 31;
#pragma unroll 1
    for (int i = 0; i < 2; i++) {
        int tok = (blockIdx.x * 8 + warp) * 2 + i;
        const float* xr = x + (size_t)tok * HDIM;
        float acc[8] = {0.f, 0.f, 0.f, 0.f, 0.f, 0.f, 0.f, 0.f};
        for (int k = lane; k < HDIM; k += 32) {
            float xv = xr[k];
#pragma unroll
            for (int e = 0; e < 8; e++) acc[e] += xv * sgw[e * HDIM + k];
        }
#pragma unroll
        for (int e = 0; e < 8; e++) {
            float v = acc[e];
#pragma unroll
            for (int o = 16; o; o >>= 1) v += __shfl_xor_sync(0xFFFFFFFFu, v, o);
            if (lane == 0) out[(size_t)tok * 8 + e] = v;
        }
    }
}

// ---------------------------------------------------------------------------
extern "C" void kernel_launch(void* const* d_in, const int* in_sizes, int n_in,
                              void* d_out, int out_size)
{
    const float* x  = (const float*)d_in[0];
    const float* gw = (const float*)d_in[1];
    const float* w1 = (const float*)d_in[2];
    const float* w2 = (const float*)d_in[3];
    const float* w3 = (const float*)d_in[4];
    const float* u1 = (const float*)d_in[5];
    const float* v1 = (const float*)d_in[6];
    const float* u2 = (const float*)d_in[7];
    const float* v2 = (const float*)d_in[8];
    const float* u3 = (const float*)d_in[9];
    const float* v3 = (const float*)d_in[10];

    float* out    = (float*)d_out;
    float* logits = out + (size_t)NTOK * HDIM;

    __nv_bfloat16 *xs, *u1s, *u3s, *u2s, *v1ts, *v3ts, *v2ts;
    __nv_bfloat16 *w1ps, *w3ps, *w2ps, *hs;
    cudaGetSymbolAddress((void**)&xs,   g_xs);
    cudaGetSymbolAddress((void**)&u1s,  g_u1s);
    cudaGetSymbolAddress((void**)&u3s,  g_u3s);
    cudaGetSymbolAddress((void**)&u2s,  g_u2s);
    cudaGetSymbolAddress((void**)&v1ts, g_v1ts);
    cudaGetSymbolAddress((void**)&v3ts, g_v3ts);
    cudaGetSymbolAddress((void**)&v2ts, g_v2ts);
    cudaGetSymbolAddress((void**)&w1ps, g_w1ps);
    cudaGetSymbolAddress((void**)&w3ps, g_w3ps);
    cudaGetSymbolAddress((void**)&w2ps, g_w2ps);
    cudaGetSymbolAddress((void**)&hs,   g_hs);

    cudaFuncSetAttribute(prep_kernel,   cudaFuncAttributeMaxDynamicSharedMemorySize, SMEM32);
    cudaFuncSetAttribute(down_kernel,   cudaFuncAttributeMaxDynamicSharedMemorySize, SMEM_TOTAL);
    cudaFuncSetAttribute(fused_gateup,  cudaFuncAttributeMaxDynamicSharedMemorySize, SMEM_TOTAL);
    cudaFuncSetAttribute(logits_kernel, cudaFuncAttributeMaxDynamicSharedMemorySize, 8 * HDIM * 4);

    // ---- splits / transposes ----------------------------------------------
    xsplit_kernel<<<dim3(1, NTOK), 256>>>(x, xs, P_X);
    usplit_kernel<<<dim3(1, IDIM, 3), 128>>>(u1, u3, u2, u1s, u3s, u2s);
    tsplit_kernel<<<dim3(IDIM / 32, RPAD / 32, 3), dim3(32, 32)>>>(
        v1, v3, v2, v1ts, v3ts, v2ts);

    dim3 blk(256);

    // ---- weight folding (128x64 tiles, 2 CTAs/SM) -------------------------
    prep_kernel<<<dim3(56, 32, 3), blk, SMEM32>>>(
        u1s, u3s, u2s, v1ts, v3ts, v2ts, w1, w3, w2, w1ps, w3ps, w2ps);

    // ---- fused gate/up + silu -> h planes ---------------------------------
    fused_gateup<<<dim3(IDIM / 64, NTOK / BM), blk, SMEM_TOTAL>>>(
        xs, w1ps, w3ps, hs);

    // ---- out = h @ W2'^T --------------------------------------------------
    down_kernel<<<dim3(HDIM / BN, NTOK / BM), blk, SMEM_TOTAL>>>(hs, w2ps, out);

    // ---- router logits (SMEM-cached gw) -----------------------------------
    logits_kernel<<<512, 256, 8 * HDIM * 4>>>(x, gw, logits);
}

// round 15
// speedup vs baseline: 1.0229x; 1.0038x over previous
#include <cuda_runtime.h>
#include <cuda_bf16.h>
#include <cstdint>
#include <cstddef>

// ---------------------------------------------------------------------------
// Merge_MixtralSparseMoeBlock — weight-folded, bf16 hi/lo split (3 passes):
//   W1' = w1 + u1@v1 ; W3' = w3 + u3@v3 ; W2' = w2 + u2@v2   (prep, 2 CTA/SM)
//   gate = x@W1'^T ; up = x@W3'^T  (fused, shared A tiles)
//   h = silu(gate)*up  (fused epilogue -> bf16 hi/lo planes)
//   out = h@W2'^T ; logits = x@gate_w^T
// R15: R14 kernels unchanged; kernel_launch forks a side stream so
//      logits + xsplit overlap with usplit/tsplit/prep (graph fork/join).
// ---------------------------------------------------------------------------

#define NTOK 8192
#define HDIM 2048
#define IDIM 7168
#define RDIM 398
#define RPAD 448

// ---------------- device scratch -------------------------------------------
__device__ __align__(16) __nv_bfloat16 g_xs  [2ull * NTOK * HDIM];
__device__ __align__(16) __nv_bfloat16 g_u1s [2ull * IDIM * RPAD];
__device__ __align__(16) __nv_bfloat16 g_u3s [2ull * IDIM * RPAD];
__device__ __align__(16) __nv_bfloat16 g_u2s [2ull * HDIM * RPAD];
__device__ __align__(16) __nv_bfloat16 g_v1ts[2ull * HDIM * RPAD];
__device__ __align__(16) __nv_bfloat16 g_v3ts[2ull * HDIM * RPAD];
__device__ __align__(16) __nv_bfloat16 g_v2ts[2ull * IDIM * RPAD];
__device__ __align__(16) __nv_bfloat16 g_w1ps[2ull * IDIM * HDIM];
__device__ __align__(16) __nv_bfloat16 g_w3ps[2ull * IDIM * HDIM];
__device__ __align__(16) __nv_bfloat16 g_w2ps[2ull * HDIM * IDIM];
__device__ __align__(16) __nv_bfloat16 g_hs  [2ull * NTOK * IDIM];

// ---------------- PTX helpers ----------------------------------------------
__device__ __forceinline__ uint32_t smem_u32(const void* p) {
    uint32_t a;
    asm("{ .reg .u64 t; cvta.to.shared.u64 t, %1; cvt.u32.u64 %0, t; }"
        : "=r"(a) : "l"(p));
    return a;
}
__device__ __forceinline__ void ldsm_x4(uint32_t* r, uint32_t addr) {
    asm volatile("ldmatrix.sync.aligned.m8n8.x4.shared.b16 {%0,%1,%2,%3}, [%4];"
                 : "=r"(r[0]), "=r"(r[1]), "=r"(r[2]), "=r"(r[3]) : "r"(addr));
}
__device__ __forceinline__ void mma_bf16(float* d, const uint32_t* a, const uint32_t* b) {
    asm volatile("mma.sync.aligned.m16n8k16.row.col.f32.bf16.bf16.f32 "
                 "{%0,%1,%2,%3}, {%4,%5,%6,%7}, {%8,%9}, {%0,%1,%2,%3};"
                 : "+f"(d[0]), "+f"(d[1]), "+f"(d[2]), "+f"(d[3])
                 : "r"(a[0]), "r"(a[1]), "r"(a[2]), "r"(a[3]),
                   "r"(b[0]), "r"(b[1]));
}
#define CP_COMMIT() asm volatile("cp.async.commit_group;" ::: "memory")
#define CP_WAIT1()  asm volatile("cp.async.wait_group 1;" ::: "memory")

// BK=64: 128B rows, chunk' = c ^ (r&7).
__device__ __forceinline__ uint32_t swz(int r, int c) {
    return (uint32_t)(r * 128 + ((c ^ (r & 7)) << 4));
}
// BK=32: 64B rows, chunk' = c ^ ((r>>1)&3).
__device__ __forceinline__ uint32_t swz32(int r, int c) {
    return (uint32_t)(r * 64 + ((c ^ ((r >> 1) & 3)) << 4));
}
__device__ __forceinline__ float siluf(float x) { return x / (1.f + __expf(-x)); }

__device__ __forceinline__ void split2(float v0, float v1,
                                       __nv_bfloat162& h, __nv_bfloat162& l) {
    __nv_bfloat16 h0 = __float2bfloat16(v0), h1 = __float2bfloat16(v1);
    __nv_bfloat16 l0 = __float2bfloat16(v0 - __bfloat162float(h0));
    __nv_bfloat16 l1 = __float2bfloat16(v1 - __bfloat162float(h1));
    h = __halves2bfloat162(h0, h1);
    l = __halves2bfloat162(l0, l1);
}

#define BM 128
#define BN 128
#define BK 64
#define STAGES 3
#define PLANE_BYTES  16384
#define STAGE_BYTES  (4 * PLANE_BYTES)
#define SMEM_TOTAL   (STAGES * STAGE_BYTES)    // 192 KB

__device__ __forceinline__ void load_plane(const __nv_bfloat16* __restrict__ g,
                                           int ld, int row0, int k0,
                                           uint32_t sbase, int t) {
#pragma unroll
    for (int i = 0; i < 4; i++) {
        int idx = i * 256 + t;
        int r = idx >> 3;
        int c = idx & 7;
        const void* gp = (const void*)(g + (size_t)(row0 + r) * ld + k0 + c * 8);
        uint32_t sp = sbase + swz(r, c);
        asm volatile("cp.async.cg.shared.global [%0], [%1], 16, 16;"
                     :: "r"(sp), "l"(gp));
    }
}
__device__ __forceinline__ void load_plane64(const __nv_bfloat16* __restrict__ g,
                                             int ld, int row0, int k0,
                                             uint32_t sbase, int t) {
#pragma unroll
    for (int i = 0; i < 2; i++) {
        int idx = i * 256 + t;
        int r = idx >> 3;
        int c = idx & 7;
        const void* gp = (const void*)(g + (size_t)(row0 + r) * ld + k0 + c * 8);
        uint32_t sp = sbase + swz(r, c);
        asm volatile("cp.async.cg.shared.global [%0], [%1], 16, 16;"
                     :: "r"(sp), "l"(gp));
    }
}
// BK=32 loaders (64B rows)
__device__ __forceinline__ void load32_128(const __nv_bfloat16* __restrict__ g,
                                           int ld, int row0, int k0,
                                           uint32_t sbase, int t) {
#pragma unroll
    for (int i = 0; i < 2; i++) {
        int idx = i * 256 + t;
        int r = idx >> 2;
        int c = idx & 3;
        const void* gp = (const void*)(g + (size_t)(row0 + r) * ld + k0 + c * 8);
        uint32_t sp = sbase + swz32(r, c);
        asm volatile("cp.async.cg.shared.global [%0], [%1], 16, 16;"
                     :: "r"(sp), "l"(gp));
    }
}
__device__ __forceinline__ void load32_64(const __nv_bfloat16* __restrict__ g,
                                          int ld, int row0, int k0,
                                          uint32_t sbase, int t) {
    int r = t >> 2;
    int c = t & 3;
    const void* gp = (const void*)(g + (size_t)(row0 + r) * ld + k0 + c * 8);
    uint32_t sp = sbase + swz32(r, c);
    asm volatile("cp.async.cg.shared.global [%0], [%1], 16, 16;"
                 :: "r"(sp), "l"(gp));
}

// plane sizes (compile-time)
#define P_X   ((long long)NTOK * HDIM)
#define P_UI  ((long long)IDIM * RPAD)
#define P_UH  ((long long)HDIM * RPAD)
#define P_W1  ((long long)IDIM * HDIM)
#define P_W2  ((long long)HDIM * IDIM)
#define P_H   ((long long)NTOK * IDIM)

// ---------------------------------------------------------------------------
// Down GEMM core: 128x128, BK=64.
__global__ __launch_bounds__(256, 1)
void down_kernel(const __nv_bfloat16* __restrict__ hs,
                 const __nv_bfloat16* __restrict__ w2ps,
                 float* __restrict__ out)
{
    extern __shared__ char smem[];
    const int t    = threadIdx.x;
    const int lane = t & 31;
    const int wid  = t >> 5;
    const int wm   = wid & 3;
    const int wn   = wid >> 2;
    const int m0   = blockIdx.y * BM;
    const int n0   = blockIdx.x * BN;
    const uint32_t sb0 = smem_u32(smem);
    const int CT = IDIM >> 6;

    float acc[2][8][4];
#pragma unroll
    for (int i = 0; i < 2; i++)
#pragma unroll
        for (int j = 0; j < 8; j++)
#pragma unroll
            for (int k = 0; k < 4; k++) acc[i][j][k] = 0.f;

    int amask[2]; uint32_t aoffr[2];
#pragma unroll
    for (int mt = 0; mt < 2; mt++) {
        int ar = wm * 32 + mt * 16 + (lane & 15);
        aoffr[mt] = (uint32_t)ar * 128;
        amask[mt] = ar & 7;
    }
    const int alo = lane >> 4;
    const int gq  = lane >> 3;
    int bmask[4]; uint32_t boffr[4];
#pragma unroll
    for (int nq = 0; nq < 4; nq++) {
        int nr = wn * 64 + nq * 16 + (lane & 7) + ((gq & 2) << 2);
        boffr[nq] = (uint32_t)nr * 128;
        bmask[nq] = nr & 7;
    }
    const int blo = gq & 1;

    auto issue = [&](int cc, int stage) {
        int k0 = cc * BK;
        uint32_t sb = sb0 + stage * STAGE_BYTES;
        load_plane(hs,          IDIM, m0, k0, sb,                   t);
        load_plane(hs + P_H,    IDIM, m0, k0, sb + PLANE_BYTES,     t);
        load_plane(w2ps,        IDIM, n0, k0, sb + 2 * PLANE_BYTES, t);
        load_plane(w2ps + P_W2, IDIM, n0, k0, sb + 3 * PLANE_BYTES, t);
    };

    issue(0, 0); CP_COMMIT();
    issue(1, 1); CP_COMMIT();

#pragma unroll 1
    for (int cc = 0; cc < CT; cc++) {
        CP_WAIT1();
        __syncthreads();

        const uint32_t sb = sb0 + (cc % STAGES) * STAGE_BYTES;
        const uint32_t sAh = sb, sAl = sb + PLANE_BYTES;
        const uint32_t sBh = sb + 2 * PLANE_BYTES, sBl = sb + 3 * PLANE_BYTES;

#pragma unroll
        for (int ks = 0; ks < 4; ks++) {
            const int ac = ks * 2 + alo;
            const int bc = ks * 2 + blo;
            uint32_t ah[2][4], al[2][4], bh[8][2], bl[8][2];
#pragma unroll
            for (int mt = 0; mt < 2; mt++)
                ldsm_x4(ah[mt], sAh + aoffr[mt] + (uint32_t)((ac ^ amask[mt]) << 4));
#pragma unroll
            for (int nq = 0; nq < 4; nq++) {
                uint32_t r[4];
                ldsm_x4(r, sBh + boffr[nq] + (uint32_t)((bc ^ bmask[nq]) << 4));
                bh[nq * 2][0] = r[0]; bh[nq * 2][1] = r[1];
                bh[nq * 2 + 1][0] = r[2]; bh[nq * 2 + 1][1] = r[3];
            }
#pragma unroll
            for (int mt = 0; mt < 2; mt++)
#pragma unroll
                for (int nt = 0; nt < 8; nt++) mma_bf16(acc[mt][nt], ah[mt], bh[nt]);
#pragma unroll
            for (int nq = 0; nq < 4; nq++) {
                uint32_t r[4];
                ldsm_x4(r, sBl + boffr[nq] + (uint32_t)((bc ^ bmask[nq]) << 4));
                bl[nq * 2][0] = r[0]; bl[nq * 2][1] = r[1];
                bl[nq * 2 + 1][0] = r[2]; bl[nq * 2 + 1][1] = r[3];
            }
#pragma unroll
            for (int mt = 0; mt < 2; mt++)
#pragma unroll
                for (int nt = 0; nt < 8; nt++) mma_bf16(acc[mt][nt], ah[mt], bl[nt]);
#pragma unroll
            for (int mt = 0; mt < 2; mt++)
                ldsm_x4(al[mt], sAl + aoffr[mt] + (uint32_t)((ac ^ amask[mt]) << 4));
#pragma unroll
            for (int mt = 0; mt < 2; mt++)
#pragma unroll
                for (int nt = 0; nt < 8; nt++) mma_bf16(acc[mt][nt], al[mt], bh[nt]);
        }
        int nc = cc + STAGES - 1;
        if (nc < CT) issue(nc, nc % STAGES);
        CP_COMMIT();
    }

#pragma unroll
    for (int mt = 0; mt < 2; mt++) {
        int row = m0 + wm * 32 + mt * 16 + (lane >> 2);
#pragma unroll
        for (int nt = 0; nt < 8; nt++) {
            int col = n0 + wn * 64 + nt * 8 + (lane & 3) * 2;
            *reinterpret_cast<float2*>(out + (size_t)row * HDIM + col) =
                make_float2(acc[mt][nt][0], acc[mt][nt][1]);
            *reinterpret_cast<float2*>(out + (size_t)(row + 8) * HDIM + col) =
                make_float2(acc[mt][nt][2], acc[mt][nt][3]);
        }
    }
}

// ---------------------------------------------------------------------------
// Prep: W' = w + u@v^T, 128x64 tiles, BK=32, 72 KB smem -> 2 CTAs/SM.
#define PB_A32 8192
#define PB_B32 4096
#define STG32  (2 * PB_A32 + 2 * PB_B32)
#define SMEM32 (3 * STG32)

__global__ __launch_bounds__(256, 2)
void prep_kernel(const __nv_bfloat16* __restrict__ u1s,
                 const __nv_bfloat16* __restrict__ u3s,
                 const __nv_bfloat16* __restrict__ u2s,
                 const __nv_bfloat16* __restrict__ v1ts,
                 const __nv_bfloat16* __restrict__ v3ts,
                 const __nv_bfloat16* __restrict__ v2ts,
                 const float* __restrict__ w1, const float* __restrict__ w3,
                 const float* __restrict__ w2,
                 __nv_bfloat16* __restrict__ w1ps,
                 __nv_bfloat16* __restrict__ w3ps,
                 __nv_bfloat16* __restrict__ w2ps)
{
    extern __shared__ char smem[];
    const int t    = threadIdx.x;
    const int lane = t & 31;
    const int wid  = t >> 5;
    const int wm   = wid & 3;
    const int wn   = wid >> 2;
    const int z    = blockIdx.z;

    int m0, n0;
    if (z < 2) { m0 = blockIdx.x * 128; n0 = blockIdx.y * 64; }
    else { int lt = blockIdx.y * 56 + blockIdx.x;
           m0 = (lt / 112) * 128; n0 = (lt % 112) * 64; }

    const __nv_bfloat16 *A, *B; long long pA, pB;
    const float* C; int ldc; __nv_bfloat16* Cs; long long pCs;
    if (z == 0)      { A = u1s; pA = P_UI; B = v1ts; pB = P_UH;
                       C = w1; ldc = HDIM; Cs = w1ps; pCs = P_W1; }
    else if (z == 1) { A = u3s; pA = P_UI; B = v3ts; pB = P_UH;
                       C = w3; ldc = HDIM; Cs = w3ps; pCs = P_W1; }
    else             { A = u2s; pA = P_UH; B = v2ts; pB = P_UI;
                       C = w2; ldc = IDIM; Cs = w2ps; pCs = P_W2; }

    const uint32_t sb0 = smem_u32(smem);
    const int CT = RPAD / 32;   // 14

    float acc[2][4][4];
#pragma unroll
    for (int i = 0; i < 2; i++)
#pragma unroll
        for (int j = 0; j < 4; j++)
#pragma unroll
            for (int k = 0; k < 4; k++) acc[i][j][k] = 0.f;

    int amask[2]; uint32_t aoffr[2];
#pragma unroll
    for (int mt = 0; mt < 2; mt++) {
        int ar = wm * 32 + mt * 16 + (lane & 15);
        aoffr[mt] = (uint32_t)ar * 64;
        amask[mt] = (ar >> 1) & 3;
    }
    const int alo = lane >> 4;
    const int gq  = lane >> 3;
    int bmask[2]; uint32_t boffr[2];
#pragma unroll
    for (int nq = 0; nq < 2; nq++) {
        int nr = wn * 32 + nq * 16 + (lane & 7) + ((gq & 2) << 2);
        boffr[nq] = (uint32_t)nr * 64;
        bmask[nq] = (nr >> 1) & 3;
    }
    const int blo = gq & 1;

    auto issue = [&](int cc, int stage) {
        int k0 = cc * 32;
        uint32_t sb = sb0 + stage * STG32;
        load32_128(A,      RPAD, m0, k0, sb,           t);
        load32_128(A + pA, RPAD, m0, k0, sb + PB_A32,  t);
        load32_64(B,       RPAD, n0, k0, sb + 2 * PB_A32,          t);
        load32_64(B + pB,  RPAD, n0, k0, sb + 2 * PB_A32 + PB_B32, t);
    };

    issue(0, 0); CP_COMMIT();
    issue(1, 1); CP_COMMIT();

#pragma unroll 1
    for (int cc = 0; cc < CT; cc++) {
        CP_WAIT1();
        __syncthreads();

        const uint32_t sb = sb0 + (cc % 3) * STG32;
        const uint32_t sAh = sb, sAl = sb + PB_A32;
        const uint32_t sBh = sb + 2 * PB_A32, sBl = sBh + PB_B32;

#pragma unroll
        for (int ks = 0; ks < 2; ks++) {
            const int ac = ks * 2 + alo;
            const int bc = ks * 2 + blo;
            uint32_t ah[2][4], al[2][4], bh[4][2], bl[4][2];
#pragma unroll
            for (int mt = 0; mt < 2; mt++)
                ldsm_x4(ah[mt], sAh + aoffr[mt] + (uint32_t)((ac ^ amask[mt]) << 4));
#pragma unroll
            for (int nq = 0; nq < 2; nq++) {
                uint32_t r[4];
                ldsm_x4(r, sBh + boffr[nq] + (uint32_t)((bc ^ bmask[nq]) << 4));
                bh[nq * 2][0] = r[0]; bh[nq * 2][1] = r[1];
                bh[nq * 2 + 1][0] = r[2]; bh[nq * 2 + 1][1] = r[3];
            }
#pragma unroll
            for (int mt = 0; mt < 2; mt++)
#pragma unroll
                for (int nt = 0; nt < 4; nt++) mma_bf16(acc[mt][nt], ah[mt], bh[nt]);
#pragma unroll
            for (int nq = 0; nq < 2; nq++) {
                uint32_t r[4];
                ldsm_x4(r, sBl + boffr[nq] + (uint32_t)((bc ^ bmask[nq]) << 4));
                bl[nq * 2][0] = r[0]; bl[nq * 2][1] = r[1];
                bl[nq * 2 + 1][0] = r[2]; bl[nq * 2 + 1][1] = r[3];
            }
#pragma unroll
            for (int mt = 0; mt < 2; mt++)
#pragma unroll
                for (int nt = 0; nt < 4; nt++) mma_bf16(acc[mt][nt], ah[mt], bl[nt]);
#pragma unroll
            for (int mt = 0; mt < 2; mt++)
                ldsm_x4(al[mt], sAl + aoffr[mt] + (uint32_t)((ac ^ amask[mt]) << 4));
#pragma unroll
            for (int mt = 0; mt < 2; mt++)
#pragma unroll
                for (int nt = 0; nt < 4; nt++) mma_bf16(acc[mt][nt], al[mt], bh[nt]);
        }
        int nc = cc + 2;
        if (nc < CT) issue(nc, nc % 3);
        CP_COMMIT();
    }

    __syncthreads();
    {
        const int EP = 72;
        char* sHi = smem;
        char* sLo = smem + 128 * EP * 2;
#pragma unroll
        for (int mt = 0; mt < 2; mt++) {
            int lr = wm * 32 + mt * 16 + (lane >> 2);
            int gr = m0 + lr;
#pragma unroll
            for (int nt = 0; nt < 4; nt++) {
                int lc = wn * 32 + nt * 8 + (lane & 3) * 2;
                float2 c0 = *reinterpret_cast<const float2*>(C + (size_t)gr * ldc + n0 + lc);
                float2 c1 = *reinterpret_cast<const float2*>(C + (size_t)(gr + 8) * ldc + n0 + lc);
                __nv_bfloat162 h, l;
                split2(acc[mt][nt][0] + c0.x, acc[mt][nt][1] + c0.y, h, l);
                *reinterpret_cast<__nv_bfloat162*>(sHi + (lr * EP + lc) * 2) = h;
                *reinterpret_cast<__nv_bfloat162*>(sLo + (lr * EP + lc) * 2) = l;
                split2(acc[mt][nt][2] + c1.x, acc[mt][nt][3] + c1.y, h, l);
                *reinterpret_cast<__nv_bfloat162*>(sHi + ((lr + 8) * EP + lc) * 2) = h;
                *reinterpret_cast<__nv_bfloat162*>(sLo + ((lr + 8) * EP + lc) * 2) = l;
            }
        }
        __syncthreads();
#pragma unroll
        for (int i = 0; i < 4; i++) {
            int idx = i * 256 + t;
            int row = idx >> 3;
            int ch  = idx & 7;
            uint4 v = *reinterpret_cast<const uint4*>(sHi + row * (EP * 2) + ch * 16);
            *reinterpret_cast<uint4*>(Cs + (size_t)(m0 + row) * ldc + n0 + ch * 8) = v;
            uint4 w = *reinterpret_cast<const uint4*>(sLo + row * (EP * 2) + ch * 16);
            *reinterpret_cast<uint4*>(Cs + pCs + (size_t)(m0 + row) * ldc + n0 + ch * 8) = w;
        }
    }
}

// ---------------------------------------------------------------------------
// Fused gate+up (unchanged).
#define FB1H (2 * PLANE_BYTES)
#define FB1L (FB1H + 8192)
#define FB2H (FB1L + 8192)
#define FB2L (FB2H + 8192)

__global__ __launch_bounds__(256, 1)
void fused_gateup(const __nv_bfloat16* __restrict__ xs,
                  const __nv_bfloat16* __restrict__ w1p,
                  const __nv_bfloat16* __restrict__ w3p,
                  __nv_bfloat16* __restrict__ hs)
{
    extern __shared__ char smem[];
    const int t    = threadIdx.x;
    const int lane = t & 31;
    const int wid  = t >> 5;
    const int wm   = wid & 3;
    const int wn   = wid >> 2;
    const int m0   = blockIdx.y * BM;
    const int n0   = blockIdx.x * 64;
    const uint32_t sb0 = smem_u32(smem);
    const int CT = HDIM >> 6;

    float accG[2][4][4], accU[2][4][4];
#pragma unroll
    for (int i = 0; i < 2; i++)
#pragma unroll
        for (int j = 0; j < 4; j++)
#pragma unroll
            for (int k = 0; k < 4; k++) { accG[i][j][k] = 0.f; accU[i][j][k] = 0.f; }

    int amask[2]; uint32_t aoffr[2];
#pragma unroll
    for (int mt = 0; mt < 2; mt++) {
        int ar = wm * 32 + mt * 16 + (lane & 15);
        aoffr[mt] = (uint32_t)ar * 128;
        amask[mt] = ar & 7;
    }
    const int alo = lane >> 4;
    const int gq  = lane >> 3;
    int bmask[2]; uint32_t boffr[2];
#pragma unroll
    for (int nq = 0; nq < 2; nq++) {
        int nr = wn * 32 + nq * 16 + (lane & 7) + ((gq & 2) << 2);
        boffr[nq] = (uint32_t)nr * 128;
        bmask[nq] = nr & 7;
    }
    const int blo = gq & 1;

    auto issue = [&](int cc, int stage) {
        int k0 = cc * BK;
        uint32_t sb = sb0 + stage * STAGE_BYTES;
        load_plane(xs,       HDIM, m0, k0, sb,               t);
        load_plane(xs + P_X, HDIM, m0, k0, sb + PLANE_BYTES, t);
        load_plane64(w1p,        HDIM, n0, k0, sb + FB1H, t);
        load_plane64(w1p + P_W1, HDIM, n0, k0, sb + FB1L, t);
        load_plane64(w3p,        HDIM, n0, k0, sb + FB2H, t);
        load_plane64(w3p + P_W1, HDIM, n0, k0, sb + FB2L, t);
    };

    issue(0, 0); CP_COMMIT();
    issue(1, 1); CP_COMMIT();

#pragma unroll 1
    for (int cc = 0; cc < CT; cc++) {
        CP_WAIT1();
        __syncthreads();

        const uint32_t sb = sb0 + (cc % STAGES) * STAGE_BYTES;
        const uint32_t sAh = sb, sAl = sb + PLANE_BYTES;

#pragma unroll
        for (int ks = 0; ks < 4; ks++) {
            const int ac = ks * 2 + alo;
            const int bc = ks * 2 + blo;
            uint32_t ah[2][4], al[2][4];
            uint32_t b1h[4][2], b1l[4][2], b2h[4][2], b2l[4][2];
#pragma unroll
            for (int mt = 0; mt < 2; mt++)
                ldsm_x4(ah[mt], sAh + aoffr[mt] + (uint32_t)((ac ^ amask[mt]) << 4));
#pragma unroll
            for (int nq = 0; nq < 2; nq++) {
                uint32_t bo = boffr[nq] + (uint32_t)((bc ^ bmask[nq]) << 4);
                uint32_t r[4];
                ldsm_x4(r, sb + FB1H + bo);
                b1h[nq * 2][0] = r[0]; b1h[nq * 2][1] = r[1];
                b1h[nq * 2 + 1][0] = r[2]; b1h[nq * 2 + 1][1] = r[3];
                ldsm_x4(r, sb + FB2H + bo);
                b2h[nq * 2][0] = r[0]; b2h[nq * 2][1] = r[1];
                b2h[nq * 2 + 1][0] = r[2]; b2h[nq * 2 + 1][1] = r[3];
            }
#pragma unroll
            for (int mt = 0; mt < 2; mt++)
#pragma unroll
                for (int nt = 0; nt < 4; nt++) mma_bf16(accG[mt][nt], ah[mt], b1h[nt]);
#pragma unroll
            for (int mt = 0; mt < 2; mt++)
#pragma unroll
                for (int nt = 0; nt < 4; nt++) mma_bf16(accU[mt][nt], ah[mt], b2h[nt]);
#pragma unroll
            for (int nq = 0; nq < 2; nq++) {
                uint32_t bo = boffr[nq] + (uint32_t)((bc ^ bmask[nq]) << 4);
                uint32_t r[4];
                ldsm_x4(r, sb + FB1L + bo);
                b1l[nq * 2][0] = r[0]; b1l[nq * 2][1] = r[1];
                b1l[nq * 2 + 1][0] = r[2]; b1l[nq * 2 + 1][1] = r[3];
                ldsm_x4(r, sb + FB2L + bo);
                b2l[nq * 2][0] = r[0]; b2l[nq * 2][1] = r[1];
                b2l[nq * 2 + 1][0] = r[2]; b2l[nq * 2 + 1][1] = r[3];
            }
#pragma unroll
            for (int mt = 0; mt < 2; mt++)
#pragma unroll
                for (int nt = 0; nt < 4; nt++) mma_bf16(accG[mt][nt], ah[mt], b1l[nt]);
#pragma unroll
            for (int mt = 0; mt < 2; mt++)
#pragma unroll
                for (int nt = 0; nt < 4; nt++) mma_bf16(accU[mt][nt], ah[mt], b2l[nt]);
#pragma unroll
            for (int mt = 0; mt < 2; mt++)
                ldsm_x4(al[mt], sAl + aoffr[mt] + (uint32_t)((ac ^ amask[mt]) << 4));
#pragma unroll
            for (int mt = 0; mt < 2; mt++)
#pragma unroll
                for (int nt = 0; nt < 4; nt++) mma_bf16(accG[mt][nt], al[mt], b1h[nt]);
#pragma unroll
            for (int mt = 0; mt < 2; mt++)
#pragma unroll
                for (int nt = 0; nt < 4; nt++) mma_bf16(accU[mt][nt], al[mt], b2h[nt]);
        }
        int nc = cc + STAGES - 1;
        if (nc < CT) issue(nc, nc % STAGES);
        CP_COMMIT();
    }

    __syncthreads();
    {
        const int EP = 72;
        char* sHi = smem;
        char* sLo = smem + 128 * EP * 2;
#pragma unroll
        for (int mt = 0; mt < 2; mt++) {
            int lr = wm * 32 + mt * 16 + (lane >> 2);
#pragma unroll
            for (int nt = 0; nt < 4; nt++) {
                int lc = wn * 32 + nt * 8 + (lane & 3) * 2;
                __nv_bfloat162 h, l;
                split2(siluf(accG[mt][nt][0]) * accU[mt][nt][0],
                       siluf(accG[mt][nt][1]) * accU[mt][nt][1], h, l);
                *reinterpret_cast<__nv_bfloat162*>(sHi + (lr * EP + lc) * 2) = h;
                *reinterpret_cast<__nv_bfloat162*>(sLo + (lr * EP + lc) * 2) = l;
                split2(siluf(accG[mt][nt][2]) * accU[mt][nt][2],
                       siluf(accG[mt][nt][3]) * accU[mt][nt][3], h, l);
                *reinterpret_cast<__nv_bfloat162*>(sHi + ((lr + 8) * EP + lc) * 2) = h;
                *reinterpret_cast<__nv_bfloat162*>(sLo + ((lr + 8) * EP + lc) * 2) = l;
            }
        }
        __syncthreads();
#pragma unroll
        for (int i = 0; i < 4; i++) {
            int idx = i * 256 + t;
            int row = idx >> 3;
            int ch  = idx & 7;
            uint4 v = *reinterpret_cast<const uint4*>(sHi + row * (EP * 2) + ch * 16);
            *reinterpret_cast<uint4*>(hs + (size_t)(m0 + row) * IDIM + n0 + ch * 8) = v;
            uint4 w = *reinterpret_cast<const uint4*>(sLo + row * (EP * 2) + ch * 16);
            *reinterpret_cast<uint4*>(hs + P_H + (size_t)(m0 + row) * IDIM + n0 + ch * 8) = w;
        }
    }
}

// ---------------------------------------------------------------------------
__global__ void xsplit_kernel(const float* __restrict__ src,
                              __nv_bfloat16* __restrict__ dst, long long plane)
{
    int k0 = (blockIdx.x * blockDim.x + threadIdx.x) * 8;
    if (k0 >= HDIM) return;
    int row = blockIdx.y;
    const float* s = src + (size_t)row * HDIM + k0;
    float4 a = *reinterpret_cast<const float4*>(s);
    float4 b = *reinterpret_cast<const float4*>(s + 4);
    float v[8] = {a.x, a.y, a.z, a.w, b.x, b.y, b.z, b.w};
    __nv_bfloat162 hi[4], lo[4];
#pragma unroll
    for (int j = 0; j < 4; j++)
        split2(v[j * 2], v[j * 2 + 1], hi[j], lo[j]);
    size_t off = (size_t)row * HDIM + k0;
    *reinterpret_cast<uint4*>(dst + off)         = *reinterpret_cast<uint4*>(hi);
    *reinterpret_cast<uint4*>(dst + off + plane) = *reinterpret_cast<uint4*>(lo);
}

__global__ void usplit_kernel(const float* __restrict__ u1,
                              const float* __restrict__ u3,
                              const float* __restrict__ u2,
                              __nv_bfloat16* __restrict__ u1s,
                              __nv_bfloat16* __restrict__ u3s,
                              __nv_bfloat16* __restrict__ u2s)
{
    int k0 = threadIdx.x * 4;
    if (k0 >= RPAD) return;
    int row = blockIdx.y;
    const float* src; __nv_bfloat16* dst; long long plane; int rows;
    if (blockIdx.z == 0)      { src = u1; dst = u1s; plane = P_UI; rows = IDIM; }
    else if (blockIdx.z == 1) { src = u3; dst = u3s; plane = P_UI; rows = IDIM; }
    else                      { src = u2; dst = u2s; plane = P_UH; rows = HDIM; }
    if (row >= rows) return;
    const float* s = src + (size_t)row * RDIM;
    __nv_bfloat16 hi[4], lo[4];
#pragma unroll
    for (int j = 0; j < 4; j++) {
        int k = k0 + j;
        float v = (k < RDIM) ? s[k] : 0.f;
        hi[j] = __float2bfloat16(v);
        lo[j] = __float2bfloat16(v - __bfloat162float(hi[j]));
    }
    size_t off = (size_t)row * RPAD + k0;
    *reinterpret_cast<__nv_bfloat162*>(dst + off)     = __halves2bfloat162(hi[0], hi[1]);
    *reinterpret_cast<__nv_bfloat162*>(dst + off + 2) = __halves2bfloat162(hi[2], hi[3]);
    *reinterpret_cast<__nv_bfloat162*>(dst + off + plane)     = __halves2bfloat162(lo[0], lo[1]);
    *reinterpret_cast<__nv_bfloat162*>(dst + off + plane + 2) = __halves2bfloat162(lo[2], lo[3]);
}

__global__ void tsplit_kernel(const float* __restrict__ v1,
                              const float* __restrict__ v3,
                              const float* __restrict__ v2,
                              __nv_bfloat16* __restrict__ v1ts,
                              __nv_bfloat16* __restrict__ v3ts,
                              __nv_bfloat16* __restrict__ v2ts)
{
    __shared__ float sm[32][33];
    const float* src; __nv_bfloat16* dst; long long plane; int C;
    if (blockIdx.z == 0)      { src = v1; dst = v1ts; plane = P_UH; C = HDIM; }
    else if (blockIdx.z == 1) { src = v3; dst = v3ts; plane = P_UH; C = HDIM; }
    else                      { src = v2; dst = v2ts; plane = P_UI; C = IDIM; }
    int c0 = blockIdx.x * 32, r0 = blockIdx.y * 32;
    if (c0 >= C) return;
    int tx = threadIdx.x, ty = threadIdx.y;
    int r = r0 + ty;
    float v = (r < RDIM) ? src[(size_t)r * C + c0 + tx] : 0.f;
    sm[ty][tx] = v;
    __syncthreads();
    float w = sm[tx][ty];
    __nv_bfloat16 hi = __float2bfloat16(w);
    __nv_bfloat16 lo = __float2bfloat16(w - __bfloat162float(hi));
    size_t off = (size_t)(c0 + ty) * RPAD + r0 + tx;
    dst[off] = hi;
    dst[off + plane] = lo;
}

__global__ void logits_kernel(const float* __restrict__ x,
                              const float* __restrict__ gw,
                              float* __restrict__ out)
{
    extern __shared__ float sgw[];
    const int t = threadIdx.x;
    for (int i = t; i < 8 * HDIM; i += 256)
        sgw[i] = gw[i];
    __syncthreads();
    const int warp = t >> 5, lane = t & 31;
#pragma unroll 1
    for (int i = 0; i < 2; i++) {
        int tok = (blockIdx.x * 8 + warp) * 2 + i;
        const float* xr = x + (size_t)tok * HDIM;
        float acc[8] = {0.f, 0.f, 0.f, 0.f, 0.f, 0.f, 0.f, 0.f};
        for (int k = lane; k < HDIM; k += 32) {
            float xv = xr[k];
#pragma unroll
            for (int e = 0; e < 8; e++) acc[e] += xv * sgw[e * HDIM + k];
        }
#pragma unroll
        for (int e = 0; e < 8; e++) {
            float v = acc[e];
#pragma unroll
            for (int o = 16; o; o >>= 1) v += __shfl_xor_sync(0xFFFFFFFFu, v, o);
            if (lane == 0) out[(size_t)tok * 8 + e] = v;
        }
    }
}

// ---------------------------------------------------------------------------
extern "C" void kernel_launch(void* const* d_in, const int* in_sizes, int n_in,
                              void* d_out, int out_size)
{
    const float* x  = (const float*)d_in[0];
    const float* gw = (const float*)d_in[1];
    const float* w1 = (const float*)d_in[2];
    const float* w2 = (const float*)d_in[3];
    const float* w3 = (const float*)d_in[4];
    const float* u1 = (const float*)d_in[5];
    const float* v1 = (const float*)d_in[6];
    const float* u2 = (const float*)d_in[7];
    const float* v2 = (const float*)d_in[8];
    const float* u3 = (const float*)d_in[9];
    const float* v3 = (const float*)d_in[10];

    float* out    = (float*)d_out;
    float* logits = out + (size_t)NTOK * HDIM;

    __nv_bfloat16 *xs, *u1s, *u3s, *u2s, *v1ts, *v3ts, *v2ts;
    __nv_bfloat16 *w1ps, *w3ps, *w2ps, *hs;
    cudaGetSymbolAddress((void**)&xs,   g_xs);
    cudaGetSymbolAddress((void**)&u1s,  g_u1s);
    cudaGetSymbolAddress((void**)&u3s,  g_u3s);
    cudaGetSymbolAddress((void**)&u2s,  g_u2s);
    cudaGetSymbolAddress((void**)&v1ts, g_v1ts);
    cudaGetSymbolAddress((void**)&v3ts, g_v3ts);
    cudaGetSymbolAddress((void**)&v2ts, g_v2ts);
    cudaGetSymbolAddress((void**)&w1ps, g_w1ps);
    cudaGetSymbolAddress((void**)&w3ps, g_w3ps);
    cudaGetSymbolAddress((void**)&w2ps, g_w2ps);
    cudaGetSymbolAddress((void**)&hs,   g_hs);

    cudaFuncSetAttribute(prep_kernel,   cudaFuncAttributeMaxDynamicSharedMemorySize, SMEM32);
    cudaFuncSetAttribute(down_kernel,   cudaFuncAttributeMaxDynamicSharedMemorySize, SMEM_TOTAL);
    cudaFuncSetAttribute(fused_gateup,  cudaFuncAttributeMaxDynamicSharedMemorySize, SMEM_TOTAL);
    cudaFuncSetAttribute(logits_kernel, cudaFuncAttributeMaxDynamicSharedMemorySize, 8 * HDIM * 4);

    // ---- side stream: logits + xsplit overlap with the prep chain ---------
    cudaStream_t s2;
    cudaEvent_t evFork, evJoin;
    cudaStreamCreateWithFlags(&s2, cudaStreamNonBlocking);
    cudaEventCreateWithFlags(&evFork, cudaEventDisableTiming);
    cudaEventCreateWithFlags(&evJoin, cudaEventDisableTiming);

    cudaEventRecord(evFork, 0);
    cudaStreamWaitEvent(s2, evFork, 0);
    logits_kernel<<<512, 256, 8 * HDIM * 4, s2>>>(x, gw, logits);
    xsplit_kernel<<<dim3(1, NTOK), 256, 0, s2>>>(x, xs, P_X);
    cudaEventRecord(evJoin, s2);

    // ---- prep chain on the main stream ------------------------------------
    usplit_kernel<<<dim3(1, IDIM, 3), 128>>>(u1, u3, u2, u1s, u3s, u2s);
    tsplit_kernel<<<dim3(IDIM / 32, RPAD / 32, 3), dim3(32, 32)>>>(
        v1, v3, v2, v1ts, v3ts, v2ts);

    dim3 blk(256);
    prep_kernel<<<dim3(56, 32, 3), blk, SMEM32>>>(
        u1s, u3s, u2s, v1ts, v3ts, v2ts, w1, w3, w2, w1ps, w3ps, w2ps);

    // join side stream (gateup needs xs)
    cudaStreamWaitEvent(0, evJoin, 0);

    // ---- fused gate/up + silu -> h planes ---------------------------------
    fused_gateup<<<dim3(IDIM / 64, NTOK / BM), blk, SMEM_TOTAL>>>(
        xs, w1ps, w3ps, hs);

    // ---- out = h @ W2'^T --------------------------------------------------
    down_kernel<<<dim3(HDIM / BN, NTOK / BM), blk, SMEM_TOTAL>>>(hs, w2ps, out);
}